// round 3
// baseline (speedup 1.0000x reference)
#include <cuda_runtime.h>

#define PP 32768
#define LL 16
#define KK 8
#define HH 128

typedef unsigned long long u64;

// Persistent hidden states (global row indices) + precomputed feat-MLP path.
__device__ float g_h [(long long)LL * PP * HH];        // 256 MiB
__device__ float g_sf[(long long)(LL - 1) * PP * HH];  // 240 MiB

__device__ __forceinline__ float lrelu(float x) { return x > 0.0f ? x : 0.1f * x; }
__device__ __forceinline__ float relu_(float x) { return x > 0.0f ? x : 0.0f; }

__device__ __forceinline__ u64 fma2(u64 a, u64 b, u64 c) {
    u64 d;
    asm("fma.rn.f32x2 %0, %1, %2, %3;" : "=l"(d) : "l"(a), "l"(b), "l"(c));
    return d;
}
__device__ __forceinline__ float lo32(u64 v) { return __uint_as_float((unsigned)v); }
__device__ __forceinline__ float hi32(u64 v) { return __uint_as_float((unsigned)(v >> 32)); }

// ---------------------------------------------------------------------------
// k_init: h[0:P] = mlp2(delay, pi). Small; baseline-style (256 thr, 64 rows).
// ---------------------------------------------------------------------------
__global__ void __launch_bounds__(256, 1)
k_init(const float* __restrict__ delay,
       const float* __restrict__ w1, const float* __restrict__ b1,
       const float* __restrict__ w2, const float* __restrict__ b2)
{
    extern __shared__ float smem[];
    float* s_t1 = smem;            // 64*64
    float* s_w2 = s_t1 + 64 * 64;  // 64*128
    float* s_b2 = s_w2 + 64 * 128; // 128

    const int tid  = threadIdx.x;
    const int row0 = blockIdx.x * 64;

    for (int i = tid; i < (64 * 128) / 4; i += 256)
        ((float4*)s_w2)[i] = ((const float4*)w2)[i];
    for (int i = tid; i < 128; i += 256) s_b2[i] = b2[i];
    for (int i = tid; i < 64 * 64; i += 256) {
        int r = i >> 6, c = i & 63;
        s_t1[i] = lrelu(delay[row0 + r] * w1[c] + b1[c]);
    }
    __syncthreads();

    const int w = tid >> 5, l = tid & 31;
    const int r0 = w * 8, c0 = l * 4;
    float acc[8][4];
#pragma unroll
    for (int r = 0; r < 8; r++)
#pragma unroll
        for (int c = 0; c < 4; c++) acc[r][c] = 0.0f;

#pragma unroll 4
    for (int k = 0; k < 64; k += 2) {
        float4 w0  = *(const float4*)(s_w2 + k * 128 + c0);
        float4 w1v = *(const float4*)(s_w2 + (k + 1) * 128 + c0);
#pragma unroll
        for (int r = 0; r < 8; r++) {
            float2 a = *(const float2*)(s_t1 + (r0 + r) * 64 + k);
            acc[r][0] = fmaf(a.x, w0.x, acc[r][0]); acc[r][0] = fmaf(a.y, w1v.x, acc[r][0]);
            acc[r][1] = fmaf(a.x, w0.y, acc[r][1]); acc[r][1] = fmaf(a.y, w1v.y, acc[r][1]);
            acc[r][2] = fmaf(a.x, w0.z, acc[r][2]); acc[r][2] = fmaf(a.y, w1v.z, acc[r][2]);
            acc[r][3] = fmaf(a.x, w0.w, acc[r][3]); acc[r][3] = fmaf(a.y, w1v.w, acc[r][3]);
        }
    }
#pragma unroll
    for (int r = 0; r < 8; r++) {
        float4 o;
        o.x = acc[r][0] + s_b2[c0 + 0];
        o.y = acc[r][1] + s_b2[c0 + 1];
        o.z = acc[r][2] + s_b2[c0 + 2];
        o.w = acc[r][3] + s_b2[c0 + 3];
        *(float4*)(g_h + (long long)(row0 + r0 + r) * HH + c0) = o;
    }
}

// ---------------------------------------------------------------------------
// k_sf: g_sf[g] = mlp2(feat[P+g], sf) + ne_b2, for g in [0, 15P).
// 256 threads / 64 rows / block. f32x2-packed, transposed weights.
// ---------------------------------------------------------------------------
#define SF_P1 34   // w1t pitch (k<=32)
#define SF_P2 66   // w2t pitch (k<=64)

__global__ void __launch_bounds__(256)
k_sf(const float* __restrict__ feat,
     const float* __restrict__ w1, const float* __restrict__ b1,
     const float* __restrict__ w2, const float* __restrict__ b2,
     const float* __restrict__ ne_b2)
{
    extern __shared__ float sm[];
    float* s_ft  = sm;               // 64*32   = 2048
    float* s_t   = s_ft  + 2048;     // 64*64   = 4096
    float* s_w1t = s_t   + 4096;     // 64*SF_P1= 2176
    float* s_w2t = s_w1t + 2176;     // 128*SF_P2=8448
    float* s_b1  = s_w2t + 8448;     // 64
    float* s_b2  = s_b1  + 64;       // 128

    const int tid = threadIdx.x;
    const int g0  = blockIdx.x * 64;

    // preload (transpose weights)
    for (int i = tid; i < 32 * 64; i += 256) {     // sf_w1 [k<32][c<64]
        int c = i & 63, k = i >> 6;
        s_w1t[c * SF_P1 + k] = w1[i];
    }
    for (int i = tid; i < 64 * 128; i += 256) {    // sf_w2 [k<64][c<128]
        int c = i & 127, k = i >> 7;
        s_w2t[c * SF_P2 + k] = w2[i];
    }
    for (int i = tid; i < 512; i += 256) {         // feat rows, float4
        int r = i >> 3, c4 = i & 7;
        ((float4*)(s_ft + r * 32))[c4] =
            ((const float4*)(feat + (long long)(PP + g0 + r) * 32))[c4];
    }
    for (int i = tid; i < 64; i += 256)  s_b1[i] = b1[i];
    for (int i = tid; i < 128; i += 256) s_b2[i] = b2[i] + ne_b2[i];
    __syncthreads();

    const int w = tid >> 5, l = tid & 31;
    const int r0 = w * 8;

    // stage 1: k=32 -> 64 cols (lane cols l, l+32); pair over k
    {
        u64 acc1[8][2];
#pragma unroll
        for (int r = 0; r < 8; r++) { acc1[r][0] = 0ull; acc1[r][1] = 0ull; }
        const float* wa = s_w1t + l * SF_P1;
        const float* wb = s_w1t + (l + 32) * SF_P1;
#pragma unroll
        for (int k = 0; k < 32; k += 4) {
            u64 wA0 = *(const u64*)(wa + k), wA1 = *(const u64*)(wa + k + 2);
            u64 wB0 = *(const u64*)(wb + k), wB1 = *(const u64*)(wb + k + 2);
#pragma unroll
            for (int r = 0; r < 8; r++) {
                ulonglong2 a = *(const ulonglong2*)(s_ft + (r0 + r) * 32 + k);
                acc1[r][0] = fma2(a.x, wA0, acc1[r][0]); acc1[r][0] = fma2(a.y, wA1, acc1[r][0]);
                acc1[r][1] = fma2(a.x, wB0, acc1[r][1]); acc1[r][1] = fma2(a.y, wB1, acc1[r][1]);
            }
        }
#pragma unroll
        for (int r = 0; r < 8; r++) {
            s_t[(r0 + r) * 64 + l]      = lrelu(lo32(acc1[r][0]) + hi32(acc1[r][0]) + s_b1[l]);
            s_t[(r0 + r) * 64 + l + 32] = lrelu(lo32(acc1[r][1]) + hi32(acc1[r][1]) + s_b1[l + 32]);
        }
        __syncwarp();
    }

    // stage 2: k=64 -> 128 cols (lane cols l+32*ci)
    {
        u64 acc2[8][4];
#pragma unroll
        for (int r = 0; r < 8; r++)
#pragma unroll
            for (int ci = 0; ci < 4; ci++) acc2[r][ci] = 0ull;
        const float* wp0 = s_w2t + l * SF_P2;
        const float* wp1 = s_w2t + (l + 32) * SF_P2;
        const float* wp2 = s_w2t + (l + 64) * SF_P2;
        const float* wp3 = s_w2t + (l + 96) * SF_P2;
#pragma unroll 4
        for (int k = 0; k < 64; k += 4) {
            u64 w0[4], w1v[4];
            w0[0] = *(const u64*)(wp0 + k); w1v[0] = *(const u64*)(wp0 + k + 2);
            w0[1] = *(const u64*)(wp1 + k); w1v[1] = *(const u64*)(wp1 + k + 2);
            w0[2] = *(const u64*)(wp2 + k); w1v[2] = *(const u64*)(wp2 + k + 2);
            w0[3] = *(const u64*)(wp3 + k); w1v[3] = *(const u64*)(wp3 + k + 2);
#pragma unroll
            for (int r = 0; r < 8; r++) {
                ulonglong2 a = *(const ulonglong2*)(s_t + (r0 + r) * 64 + k);
#pragma unroll
                for (int ci = 0; ci < 4; ci++) {
                    acc2[r][ci] = fma2(a.x, w0[ci],  acc2[r][ci]);
                    acc2[r][ci] = fma2(a.y, w1v[ci], acc2[r][ci]);
                }
            }
        }
#pragma unroll
        for (int r = 0; r < 8; r++) {
            float* dst = g_sf + (long long)(g0 + r0 + r) * HH;
#pragma unroll
            for (int ci = 0; ci < 4; ci++) {
                int c = l + 32 * ci;
                dst[c] = lo32(acc2[r][ci]) + hi32(acc2[r][ci]) + s_b2[c];
            }
        }
    }
}

// ---------------------------------------------------------------------------
// k_layer<DO_RELU>: 512 threads / 128 rows / block.
//   neigh = mean_k h[pred];  t = lrelu(neigh@ne_w1+ne_b1);
//   hn = t@ne_w2 + g_sf[row];  relu if DO_RELU;  store g_h.
// ---------------------------------------------------------------------------
#define LY_P1 130  // w1t pitch (k<=128)
#define LY_P2 66   // w2t pitch (k<=64)

template <bool DO_RELU>
__global__ void __launch_bounds__(512, 1)
k_layer(int lo, long long sfoff,
        const int*   __restrict__ pred,   // this layer's slice: PP*KK
        const float* __restrict__ w1, const float* __restrict__ b1,
        const float* __restrict__ w2)
{
    extern __shared__ float sm[];
    float* s_nt  = sm;                 // 128*128 = 16384
    float* s_t   = s_nt  + 16384;      // 128*64  = 8192
    float* s_w1t = s_t   + 8192;       // 64*LY_P1= 8320
    float* s_w2t = s_w1t + 8320;       // 128*LY_P2=8448
    float* s_b1  = s_w2t + 8448;       // 64
    int*   s_pred= (int*)(s_b1 + 64);  // 128*8 = 1024

    const int tid  = threadIdx.x;
    const int row0 = blockIdx.x * 128;

    // preload (transpose weights) + pred
    for (int i = tid; i < 1024; i += 512)
        s_pred[i] = pred[row0 * KK + i];
    for (int i = tid; i < 128 * 64; i += 512) {    // ne_w1 [k<128][c<64]
        int c = i & 63, k = i >> 6;
        s_w1t[c * LY_P1 + k] = w1[i];
    }
    for (int i = tid; i < 64 * 128; i += 512) {    // ne_w2 [k<64][c<128]
        int c = i & 127, k = i >> 7;
        s_w2t[c * LY_P2 + k] = w2[i];
    }
    for (int i = tid; i < 64; i += 512) s_b1[i] = b1[i];
    __syncthreads();

    // gather mean of 8 predecessor rows: 128 rows x 32 float4-cols = 4096 tasks
#pragma unroll
    for (int j = 0; j < 8; j++) {
        int task = tid + j * 512;
        int r = task >> 5, c4 = task & 31;
        const int* pr = s_pred + r * 8;
        float x = 0.f, y = 0.f, z = 0.f, ww = 0.f;
#pragma unroll
        for (int k = 0; k < 8; k++) {
            const float4 v = *((const float4*)(g_h + (long long)pr[k] * HH) + c4);
            x += v.x; y += v.y; z += v.z; ww += v.w;
        }
        *((float4*)(s_nt + r * 128) + c4) =
            make_float4(x * 0.125f, y * 0.125f, z * 0.125f, ww * 0.125f);
    }
    __syncthreads();

    const int w = tid >> 5, l = tid & 31;   // 16 warps, 8 rows each
    const int r0 = w * 8;

    // stage 1: k=128 -> 64 cols (lane cols l, l+32); f32x2 paired over k
    {
        u64 acc1[8][2];
#pragma unroll
        for (int r = 0; r < 8; r++) { acc1[r][0] = 0ull; acc1[r][1] = 0ull; }
        const float* wa = s_w1t + l * LY_P1;
        const float* wb = s_w1t + (l + 32) * LY_P1;
#pragma unroll 4
        for (int k = 0; k < 128; k += 4) {
            u64 wA0 = *(const u64*)(wa + k), wA1 = *(const u64*)(wa + k + 2);
            u64 wB0 = *(const u64*)(wb + k), wB1 = *(const u64*)(wb + k + 2);
#pragma unroll
            for (int r = 0; r < 8; r++) {
                ulonglong2 a = *(const ulonglong2*)(s_nt + (r0 + r) * 128 + k);
                acc1[r][0] = fma2(a.x, wA0, acc1[r][0]); acc1[r][0] = fma2(a.y, wA1, acc1[r][0]);
                acc1[r][1] = fma2(a.x, wB0, acc1[r][1]); acc1[r][1] = fma2(a.y, wB1, acc1[r][1]);
            }
        }
#pragma unroll
        for (int r = 0; r < 8; r++) {
            s_t[(r0 + r) * 64 + l]      = lrelu(lo32(acc1[r][0]) + hi32(acc1[r][0]) + s_b1[l]);
            s_t[(r0 + r) * 64 + l + 32] = lrelu(lo32(acc1[r][1]) + hi32(acc1[r][1]) + s_b1[l + 32]);
        }
        __syncwarp();   // cross-lane reads of s_t below, warp-local rows only
    }

    // stage 2: k=64 -> 128 cols (lane cols l+32*ci)
    {
        u64 acc2[8][4];
#pragma unroll
        for (int r = 0; r < 8; r++)
#pragma unroll
            for (int ci = 0; ci < 4; ci++) acc2[r][ci] = 0ull;
        const float* wp0 = s_w2t + l * LY_P2;
        const float* wp1 = s_w2t + (l + 32) * LY_P2;
        const float* wp2 = s_w2t + (l + 64) * LY_P2;
        const float* wp3 = s_w2t + (l + 96) * LY_P2;
#pragma unroll 4
        for (int k = 0; k < 64; k += 4) {
            u64 w0[4], w1v[4];
            w0[0] = *(const u64*)(wp0 + k); w1v[0] = *(const u64*)(wp0 + k + 2);
            w0[1] = *(const u64*)(wp1 + k); w1v[1] = *(const u64*)(wp1 + k + 2);
            w0[2] = *(const u64*)(wp2 + k); w1v[2] = *(const u64*)(wp2 + k + 2);
            w0[3] = *(const u64*)(wp3 + k); w1v[3] = *(const u64*)(wp3 + k + 2);
#pragma unroll
            for (int r = 0; r < 8; r++) {
                ulonglong2 a = *(const ulonglong2*)(s_t + (r0 + r) * 64 + k);
#pragma unroll
                for (int ci = 0; ci < 4; ci++) {
                    acc2[r][ci] = fma2(a.x, w0[ci],  acc2[r][ci]);
                    acc2[r][ci] = fma2(a.y, w1v[ci], acc2[r][ci]);
                }
            }
        }
#pragma unroll
        for (int r = 0; r < 8; r++) {
            const float* sfrow = g_sf + sfoff + (long long)(row0 + r0 + r) * HH;
            float*       dst   = g_h + (long long)(lo + row0 + r0 + r) * HH;
#pragma unroll
            for (int ci = 0; ci < 4; ci++) {
                int c = l + 32 * ci;
                float v = lo32(acc2[r][ci]) + hi32(acc2[r][ci]) + sfrow[c];
                if (DO_RELU) v = relu_(v);
                dst[c] = v;
            }
        }
    }
}

// ---------------------------------------------------------------------------
// k_final: h_glob = mlp2(PO_feat, gl); out = mlp2([h_gnn | h_glob], out)
// (unchanged from passing version)
// ---------------------------------------------------------------------------
__global__ void __launch_bounds__(256, 1)
k_final(const float* __restrict__ PO,
        const float* __restrict__ gl_w1, const float* __restrict__ gl_b1,
        const float* __restrict__ gl_w2, const float* __restrict__ gl_b2,
        const float* __restrict__ out_w1, const float* __restrict__ out_b1,
        const float* __restrict__ out_w2, const float* __restrict__ out_b2,
        float* __restrict__ out)
{
    extern __shared__ float smem[];
    float* s_x   = smem;             // 64*256
    float* s_w   = s_x + 16384;      // 64*128
    float* s_t   = s_w + 8192;       // 64*132
    float* s_g1  = s_t + 8448;       // 64*64
    float* s_gb2 = s_g1 + 4096;      // 128
    float* s_ob1 = s_gb2 + 128;      // 128
    float* s_ow2 = s_ob1 + 128;      // 128

    const int tid  = threadIdx.x;
    const int row0 = blockIdx.x * 64;
    const long long gnn0 = (long long)(LL - 1) * PP * HH;

    for (int i = tid; i < 2048; i += 256)
        ((float4*)s_w)[i] = ((const float4*)gl_w2)[i];
    for (int i = tid; i < 128; i += 256) {
        s_gb2[i] = gl_b2[i];
        s_ob1[i] = out_b1[i];
        s_ow2[i] = out_w2[i];
    }
    for (int i = tid; i < 64 * 64; i += 256) {
        int r = i >> 6, c = i & 63;
        s_g1[i] = lrelu(PO[row0 + r] * gl_w1[c] + gl_b1[c]);
    }
    for (int i = tid; i < 2048; i += 256) {
        int r = i >> 5, c4 = i & 31;
        float4 v = *((const float4*)(g_h + gnn0 + (long long)(row0 + r) * HH) + c4);
        *((float4*)(s_x + r * 256) + c4) = v;
    }
    __syncthreads();

    const int w = tid >> 5, l = tid & 31;
    const int r0 = w * 8, c0 = l * 4;

    {
        float acc[8][4];
#pragma unroll
        for (int r = 0; r < 8; r++) { acc[r][0] = acc[r][1] = acc[r][2] = acc[r][3] = 0.f; }
#pragma unroll 4
        for (int k = 0; k < 64; k += 2) {
            float4 w0  = *(const float4*)(s_w + k * 128 + c0);
            float4 w1v = *(const float4*)(s_w + (k + 1) * 128 + c0);
#pragma unroll
            for (int r = 0; r < 8; r++) {
                float2 a = *(const float2*)(s_g1 + (r0 + r) * 64 + k);
                acc[r][0] = fmaf(a.x, w0.x, acc[r][0]); acc[r][0] = fmaf(a.y, w1v.x, acc[r][0]);
                acc[r][1] = fmaf(a.x, w0.y, acc[r][1]); acc[r][1] = fmaf(a.y, w1v.y, acc[r][1]);
                acc[r][2] = fmaf(a.x, w0.z, acc[r][2]); acc[r][2] = fmaf(a.y, w1v.z, acc[r][2]);
                acc[r][3] = fmaf(a.x, w0.w, acc[r][3]); acc[r][3] = fmaf(a.y, w1v.w, acc[r][3]);
            }
        }
#pragma unroll
        for (int r = 0; r < 8; r++) {
            float4 o;
            o.x = acc[r][0] + s_gb2[c0 + 0];
            o.y = acc[r][1] + s_gb2[c0 + 1];
            o.z = acc[r][2] + s_gb2[c0 + 2];
            o.w = acc[r][3] + s_gb2[c0 + 3];
            *(float4*)(s_x + (r0 + r) * 256 + 128 + c0) = o;
        }
    }

    float acc[8][4];
#pragma unroll
    for (int r = 0; r < 8; r++) { acc[r][0] = acc[r][1] = acc[r][2] = acc[r][3] = 0.f; }
    for (int kt = 0; kt < 4; kt++) {
        __syncthreads();
        const float4* src = (const float4*)(out_w1 + kt * 64 * 128);
        for (int i = tid; i < 2048; i += 256) ((float4*)s_w)[i] = src[i];
        __syncthreads();
#pragma unroll 4
        for (int k = 0; k < 64; k += 2) {
            float4 w0  = *(const float4*)(s_w + k * 128 + c0);
            float4 w1v = *(const float4*)(s_w + (k + 1) * 128 + c0);
#pragma unroll
            for (int r = 0; r < 8; r++) {
                float2 a = *(const float2*)(s_x + (r0 + r) * 256 + kt * 64 + k);
                acc[r][0] = fmaf(a.x, w0.x, acc[r][0]); acc[r][0] = fmaf(a.y, w1v.x, acc[r][0]);
                acc[r][1] = fmaf(a.x, w0.y, acc[r][1]); acc[r][1] = fmaf(a.y, w1v.y, acc[r][1]);
                acc[r][2] = fmaf(a.x, w0.z, acc[r][2]); acc[r][2] = fmaf(a.y, w1v.z, acc[r][2]);
                acc[r][3] = fmaf(a.x, w0.w, acc[r][3]); acc[r][3] = fmaf(a.y, w1v.w, acc[r][3]);
            }
        }
    }
#pragma unroll
    for (int r = 0; r < 8; r++) {
        float* t = s_t + (r0 + r) * 132;
        t[c0 + 0] = lrelu(acc[r][0] + s_ob1[c0 + 0]);
        t[c0 + 1] = lrelu(acc[r][1] + s_ob1[c0 + 1]);
        t[c0 + 2] = lrelu(acc[r][2] + s_ob1[c0 + 2]);
        t[c0 + 3] = lrelu(acc[r][3] + s_ob1[c0 + 3]);
    }
    __syncthreads();

    if (tid < 64) {
        float s = out_b2[0];
        const float* t = s_t + tid * 132;
#pragma unroll 8
        for (int k = 0; k < 128; k++) s = fmaf(t[k], s_ow2[k], s);
        out[row0 + tid] = s;
    }
}

// ---------------------------------------------------------------------------
extern "C" void kernel_launch(void* const* d_in, const int* in_sizes, int n_in,
                              void* d_out, int out_size)
{
    // Disambiguate input ordering via in_sizes[3] (pred=3932160 vs pi_w1=64).
    int idx_pred, idx_ispo, wbase;
    if (in_sizes[3] == (LL - 1) * PP * KK) { idx_pred = 3; idx_ispo = 4; wbase = 5; }
    else                                   { idx_pred = 23; idx_ispo = 24; wbase = 3; }
    (void)idx_ispo;

    const float* delay  = (const float*)d_in[0];
    const float* feat   = (const float*)d_in[1];
    const float* PO     = (const float*)d_in[2];
    const int*   pred   = (const int*)d_in[idx_pred];
    const float* pi_w1  = (const float*)d_in[wbase + 0];
    const float* pi_b1  = (const float*)d_in[wbase + 1];
    const float* pi_w2  = (const float*)d_in[wbase + 2];
    const float* pi_b2  = (const float*)d_in[wbase + 3];
    const float* ne_w1  = (const float*)d_in[wbase + 4];
    const float* ne_b1  = (const float*)d_in[wbase + 5];
    const float* ne_w2  = (const float*)d_in[wbase + 6];
    const float* ne_b2  = (const float*)d_in[wbase + 7];
    const float* sf_w1  = (const float*)d_in[wbase + 8];
    const float* sf_b1  = (const float*)d_in[wbase + 9];
    const float* sf_w2  = (const float*)d_in[wbase + 10];
    const float* sf_b2  = (const float*)d_in[wbase + 11];
    const float* gl_w1  = (const float*)d_in[wbase + 12];
    const float* gl_b1  = (const float*)d_in[wbase + 13];
    const float* gl_w2  = (const float*)d_in[wbase + 14];
    const float* gl_b2  = (const float*)d_in[wbase + 15];
    const float* out_w1 = (const float*)d_in[wbase + 16];
    const float* out_b1 = (const float*)d_in[wbase + 17];
    const float* out_w2 = (const float*)d_in[wbase + 18];
    const float* out_b2 = (const float*)d_in[wbase + 19];
    float* out = (float*)d_out;

    const size_t sh_init  = (size_t)(64 * 64 + 64 * 128 + 128) * 4;
    const size_t sh_sf    = (size_t)(2048 + 4096 + 2176 + 8448 + 64 + 128) * 4;
    const size_t sh_layer = (size_t)(16384 + 8192 + 8320 + 8448 + 64) * 4 + 1024 * 4;
    const size_t sh_final = (size_t)(16384 + 8192 + 8448 + 4096 + 128 + 128 + 128) * 4;

    cudaFuncSetAttribute(k_init,  cudaFuncAttributeMaxDynamicSharedMemorySize, (int)sh_init);
    cudaFuncSetAttribute(k_sf,    cudaFuncAttributeMaxDynamicSharedMemorySize, (int)sh_sf);
    cudaFuncSetAttribute(k_layer<true>,  cudaFuncAttributeMaxDynamicSharedMemorySize, (int)sh_layer);
    cudaFuncSetAttribute(k_layer<false>, cudaFuncAttributeMaxDynamicSharedMemorySize, (int)sh_layer);
    cudaFuncSetAttribute(k_final, cudaFuncAttributeMaxDynamicSharedMemorySize, (int)sh_final);

    // sf path for all 15 layers (independent of the chain)
    k_sf<<<(LL - 1) * PP / 64, 256, sh_sf>>>(feat, sf_w1, sf_b1, sf_w2, sf_b2, ne_b2);
    // layer 0
    k_init<<<PP / 64, 256, sh_init>>>(delay, pi_w1, pi_b1, pi_w2, pi_b2);
    // layers 1..15 (sequential chain); relu except last layer (is_po==1 there)
    for (int i = 1; i < LL; i++) {
        long long sfoff = (long long)(i - 1) * PP * HH;
        const int* pl = pred + (long long)(i - 1) * PP * KK;
        if (i < LL - 1)
            k_layer<true><<<PP / 128, 512, sh_layer>>>(i * PP, sfoff, pl, ne_w1, ne_b1, ne_w2);
        else
            k_layer<false><<<PP / 128, 512, sh_layer>>>(i * PP, sfoff, pl, ne_w1, ne_b1, ne_w2);
    }
    k_final<<<PP / 64, 256, sh_final>>>(PO, gl_w1, gl_b1, gl_w2, gl_b2,
                                        out_w1, out_b1, out_w2, out_b2, out);
}

// round 4
// speedup vs baseline: 1.4702x; 1.4702x over previous
#include <cuda_runtime.h>

#define PP 32768
#define LL 16
#define KK 8
#define HH 128
#define NROWS 64
#define NTHREADS 256

// Full h buffer for all L*P nodes (pred holds GLOBAL indices). 256 MiB static.
__device__ float g_h[(long long)LL * PP * HH];

__device__ __forceinline__ float lrelu(float x) { return x > 0.0f ? x : 0.1f * x; }
__device__ __forceinline__ float relu_(float x) { return x > 0.0f ? x : 0.0f; }

// ---------------------------------------------------------------------------
// h[0:P] = mlp2(delay, pi)
// ---------------------------------------------------------------------------
__global__ void __launch_bounds__(NTHREADS, 1)
k_init(const float* __restrict__ delay,
       const float* __restrict__ w1, const float* __restrict__ b1,
       const float* __restrict__ w2, const float* __restrict__ b2)
{
    extern __shared__ float smem[];
    float* s_t1 = smem;            // 64*64
    float* s_w2 = s_t1 + 64 * 64;  // 64*128
    float* s_b2 = s_w2 + 64 * 128; // 128

    const int tid  = threadIdx.x;
    const int row0 = blockIdx.x * NROWS;

    for (int i = tid; i < (64 * 128) / 4; i += NTHREADS)
        ((float4*)s_w2)[i] = ((const float4*)w2)[i];
    for (int i = tid; i < 128; i += NTHREADS) s_b2[i] = b2[i];
    for (int i = tid; i < 64 * 64; i += NTHREADS) {
        int r = i >> 6, c = i & 63;
        s_t1[i] = lrelu(delay[row0 + r] * w1[c] + b1[c]);
    }
    __syncthreads();

    const int w = tid >> 5, l = tid & 31;
    const int r0 = w * 8, c0 = l * 4;
    float acc[8][4];
#pragma unroll
    for (int r = 0; r < 8; r++)
#pragma unroll
        for (int c = 0; c < 4; c++) acc[r][c] = 0.0f;

#pragma unroll 4
    for (int k = 0; k < 64; k += 2) {
        float4 w0  = *(const float4*)(s_w2 + k * 128 + c0);
        float4 w1v = *(const float4*)(s_w2 + (k + 1) * 128 + c0);
#pragma unroll
        for (int r = 0; r < 8; r++) {
            float2 a = *(const float2*)(s_t1 + (r0 + r) * 64 + k);
            acc[r][0] = fmaf(a.x, w0.x, acc[r][0]); acc[r][0] = fmaf(a.y, w1v.x, acc[r][0]);
            acc[r][1] = fmaf(a.x, w0.y, acc[r][1]); acc[r][1] = fmaf(a.y, w1v.y, acc[r][1]);
            acc[r][2] = fmaf(a.x, w0.z, acc[r][2]); acc[r][2] = fmaf(a.y, w1v.z, acc[r][2]);
            acc[r][3] = fmaf(a.x, w0.w, acc[r][3]); acc[r][3] = fmaf(a.y, w1v.w, acc[r][3]);
        }
    }
#pragma unroll
    for (int r = 0; r < 8; r++) {
        float4 o;
        o.x = acc[r][0] + s_b2[c0 + 0];
        o.y = acc[r][1] + s_b2[c0 + 1];
        o.z = acc[r][2] + s_b2[c0 + 2];
        o.w = acc[r][3] + s_b2[c0 + 3];
        *(float4*)(g_h + (long long)(row0 + r0 + r) * HH + c0) = o;
    }
}

// ---------------------------------------------------------------------------
// Layer i (i=1..15). 256 thr / 64 rows, 113KB smem -> 2 blocks/SM.
//   neigh = mean_k h[pred];  t = [lrelu(neigh@ne_w1+b)|lrelu(feat@sf_w1+b)]
//   hn = t_ne@ne_w2 + t_sf@sf_w2 + (ne_b2+sf_b2);  relu (except last layer)
// Stage-2 runs in two passes over a single 32KB weight buffer (s_w2);
// pred[] overlays s_w2 during gather.
// ---------------------------------------------------------------------------
template <bool DO_RELU>
__global__ void __launch_bounds__(NTHREADS, 2)
k_layer(int lo,
        const int*   __restrict__ pred,   // this layer's slice: PP*KK
        const float* __restrict__ feat,
        const float* __restrict__ ne_w1, const float* __restrict__ ne_b1,
        const float* __restrict__ ne_w2, const float* __restrict__ ne_b2,
        const float* __restrict__ sf_w1, const float* __restrict__ sf_b1,
        const float* __restrict__ sf_w2, const float* __restrict__ sf_b2)
{
    extern __shared__ float smem[];
    float* s_nt   = smem;                 // 64*128 = 8192   (neigh, then t)
    float* s_w1ne = s_nt + 8192;          // 128*64 = 8192   [k][c]
    float* s_w1sf = s_w1ne + 8192;        // 32*64  = 2048   [k][c]
    float* s_w2   = s_w1sf + 2048;        // 64*128 = 8192   (pred overlay, then ne_w2, then sf_w2)
    float* s_ft   = s_w2 + 8192;          // 64*32  = 2048
    float* s_b1   = s_ft + 2048;          // 128
    float* s_b2   = s_b1 + 128;           // 128
    int*   s_pred = (int*)s_w2;           // 512 ints, overlay

    const int tid  = threadIdx.x;
    const int row0 = blockIdx.x * NROWS;

    // ---- cooperative preload (no w2 yet; pred lives in its buffer) ----
    for (int i = tid; i < 2048; i += NTHREADS)
        ((float4*)s_w1ne)[i] = ((const float4*)ne_w1)[i];
    for (int i = tid; i < 512; i += NTHREADS)
        ((float4*)s_w1sf)[i] = ((const float4*)sf_w1)[i];
    for (int i = tid; i < 512; i += NTHREADS) {
        int r = i >> 3, c4 = i & 7;
        ((float4*)s_ft)[i] = *((const float4*)(feat + (long long)(lo + row0 + r) * 32) + c4);
    }
    for (int i = tid; i < 512; i += NTHREADS)
        s_pred[i] = pred[(long long)row0 * KK + i];
    for (int i = tid; i < 128; i += NTHREADS) {
        s_b1[i] = (i < 64) ? ne_b1[i] : sf_b1[i - 64];
        s_b2[i] = ne_b2[i] + sf_b2[i];
    }
    __syncthreads();

    // ---- gather mean of 8 predecessor rows (warp = one h row per j) ----
#pragma unroll
    for (int j = 0; j < 8; j++) {
        int task = tid + j * NTHREADS;
        int r = task >> 5, c4 = task & 31;
        const int* pr = s_pred + r * 8;
        float x = 0.f, y = 0.f, z = 0.f, ww = 0.f;
#pragma unroll
        for (int k = 0; k < 8; k++) {
            const float4 v = *((const float4*)(g_h + (long long)pr[k] * HH) + c4);
            x += v.x; y += v.y; z += v.z; ww += v.w;
        }
        *((float4*)(s_nt + r * 128) + c4) =
            make_float4(x * 0.125f, y * 0.125f, z * 0.125f, ww * 0.125f);
    }
    __syncthreads();   // gather done; s_pred dead -> s_w2 reusable

    // ---- fill s_w2 with ne_w2 (overlaps stage-1 compute latency-wise) ----
    for (int i = tid; i < 2048; i += NTHREADS)
        ((float4*)s_w2)[i] = ((const float4*)ne_w2)[i];

    const int w = tid >> 5, l = tid & 31;
    const int r0 = w * 8;
    const int cA = l * 2;

    // ---- stage 1: ne path (k=128 over neigh) + sf path (k=32 over feat) ----
    float accA[8][2], accB[8][2];
#pragma unroll
    for (int r = 0; r < 8; r++) { accA[r][0] = accA[r][1] = accB[r][0] = accB[r][1] = 0.f; }

#pragma unroll 4
    for (int k = 0; k < 128; k += 2) {
        float2 w0  = *(const float2*)(s_w1ne + k * 64 + cA);
        float2 w1v = *(const float2*)(s_w1ne + (k + 1) * 64 + cA);
#pragma unroll
        for (int r = 0; r < 8; r++) {
            float2 a = *(const float2*)(s_nt + (r0 + r) * 128 + k);
            accA[r][0] = fmaf(a.x, w0.x, accA[r][0]); accA[r][0] = fmaf(a.y, w1v.x, accA[r][0]);
            accA[r][1] = fmaf(a.x, w0.y, accA[r][1]); accA[r][1] = fmaf(a.y, w1v.y, accA[r][1]);
        }
    }
#pragma unroll
    for (int k = 0; k < 32; k += 2) {
        float2 w0  = *(const float2*)(s_w1sf + k * 64 + cA);
        float2 w1v = *(const float2*)(s_w1sf + (k + 1) * 64 + cA);
#pragma unroll
        for (int r = 0; r < 8; r++) {
            float2 a = *(const float2*)(s_ft + (r0 + r) * 32 + k);
            accB[r][0] = fmaf(a.x, w0.x, accB[r][0]); accB[r][0] = fmaf(a.y, w1v.x, accB[r][0]);
            accB[r][1] = fmaf(a.x, w0.y, accB[r][1]); accB[r][1] = fmaf(a.y, w1v.y, accB[r][1]);
        }
    }
    __syncthreads();   // all reads of s_nt done; ne_w2 STS drained

    // t overwrites s_nt: [t_ne(64) | t_sf(64)] per row
#pragma unroll
    for (int r = 0; r < 8; r++) {
        float* t = s_nt + (r0 + r) * 128;
        t[cA]          = lrelu(accA[r][0] + s_b1[cA]);
        t[cA + 1]      = lrelu(accA[r][1] + s_b1[cA + 1]);
        t[64 + cA]     = lrelu(accB[r][0] + s_b1[64 + cA]);
        t[64 + cA + 1] = lrelu(accB[r][1] + s_b1[64 + cA + 1]);
    }
    __syncthreads();

    // ---- stage 2, pass A: t_ne (k=0..63) @ ne_w2 ----
    const int c0 = l * 4;
    float acc[8][4];
#pragma unroll
    for (int r = 0; r < 8; r++) { acc[r][0] = acc[r][1] = acc[r][2] = acc[r][3] = 0.f; }
#pragma unroll 4
    for (int k = 0; k < 64; k += 2) {
        float4 w0  = *(const float4*)(s_w2 + k * 128 + c0);
        float4 w1v = *(const float4*)(s_w2 + (k + 1) * 128 + c0);
#pragma unroll
        for (int r = 0; r < 8; r++) {
            float2 a = *(const float2*)(s_nt + (r0 + r) * 128 + k);
            acc[r][0] = fmaf(a.x, w0.x, acc[r][0]); acc[r][0] = fmaf(a.y, w1v.x, acc[r][0]);
            acc[r][1] = fmaf(a.x, w0.y, acc[r][1]); acc[r][1] = fmaf(a.y, w1v.y, acc[r][1]);
            acc[r][2] = fmaf(a.x, w0.z, acc[r][2]); acc[r][2] = fmaf(a.y, w1v.z, acc[r][2]);
            acc[r][3] = fmaf(a.x, w0.w, acc[r][3]); acc[r][3] = fmaf(a.y, w1v.w, acc[r][3]);
        }
    }
    __syncthreads();   // pass A reads done; refill buffer

    for (int i = tid; i < 2048; i += NTHREADS)
        ((float4*)s_w2)[i] = ((const float4*)sf_w2)[i];
    __syncthreads();

    // ---- stage 2, pass B: t_sf (k=64..127) @ sf_w2; emit ----
#pragma unroll 4
    for (int k = 0; k < 64; k += 2) {
        float4 w0  = *(const float4*)(s_w2 + k * 128 + c0);
        float4 w1v = *(const float4*)(s_w2 + (k + 1) * 128 + c0);
#pragma unroll
        for (int r = 0; r < 8; r++) {
            float2 a = *(const float2*)(s_nt + (r0 + r) * 128 + 64 + k);
            acc[r][0] = fmaf(a.x, w0.x, acc[r][0]); acc[r][0] = fmaf(a.y, w1v.x, acc[r][0]);
            acc[r][1] = fmaf(a.x, w0.y, acc[r][1]); acc[r][1] = fmaf(a.y, w1v.y, acc[r][1]);
            acc[r][2] = fmaf(a.x, w0.z, acc[r][2]); acc[r][2] = fmaf(a.y, w1v.z, acc[r][2]);
            acc[r][3] = fmaf(a.x, w0.w, acc[r][3]); acc[r][3] = fmaf(a.y, w1v.w, acc[r][3]);
        }
    }
#pragma unroll
    for (int r = 0; r < 8; r++) {
        float4 o;
        o.x = acc[r][0] + s_b2[c0 + 0];
        o.y = acc[r][1] + s_b2[c0 + 1];
        o.z = acc[r][2] + s_b2[c0 + 2];
        o.w = acc[r][3] + s_b2[c0 + 3];
        if (DO_RELU) { o.x = relu_(o.x); o.y = relu_(o.y); o.z = relu_(o.z); o.w = relu_(o.w); }
        *(float4*)(g_h + (long long)(lo + row0 + r0 + r) * HH + c0) = o;
    }
}

// ---------------------------------------------------------------------------
// Final head: h_glob = mlp2(PO_feat, gl); out = mlp2([h_gnn | h_glob], out)
// ---------------------------------------------------------------------------
__global__ void __launch_bounds__(NTHREADS, 1)
k_final(const float* __restrict__ PO,
        const float* __restrict__ gl_w1, const float* __restrict__ gl_b1,
        const float* __restrict__ gl_w2, const float* __restrict__ gl_b2,
        const float* __restrict__ out_w1, const float* __restrict__ out_b1,
        const float* __restrict__ out_w2, const float* __restrict__ out_b2,
        float* __restrict__ out)
{
    extern __shared__ float smem[];
    float* s_x   = smem;             // 64*256
    float* s_w   = s_x + 16384;      // 64*128
    float* s_t   = s_w + 8192;       // 64*132
    float* s_g1  = s_t + 8448;       // 64*64
    float* s_gb2 = s_g1 + 4096;      // 128
    float* s_ob1 = s_gb2 + 128;      // 128
    float* s_ow2 = s_ob1 + 128;      // 128

    const int tid  = threadIdx.x;
    const int row0 = blockIdx.x * NROWS;
    const long long gnn0 = (long long)(LL - 1) * PP * HH;

    for (int i = tid; i < 2048; i += NTHREADS)
        ((float4*)s_w)[i] = ((const float4*)gl_w2)[i];
    for (int i = tid; i < 128; i += NTHREADS) {
        s_gb2[i] = gl_b2[i];
        s_ob1[i] = out_b1[i];
        s_ow2[i] = out_w2[i];
    }
    for (int i = tid; i < 64 * 64; i += NTHREADS) {
        int r = i >> 6, c = i & 63;
        s_g1[i] = lrelu(PO[row0 + r] * gl_w1[c] + gl_b1[c]);
    }
    for (int i = tid; i < 2048; i += NTHREADS) {
        int r = i >> 5, c4 = i & 31;
        float4 v = *((const float4*)(g_h + gnn0 + (long long)(row0 + r) * HH) + c4);
        *((float4*)(s_x + r * 256) + c4) = v;
    }
    __syncthreads();

    const int w = tid >> 5, l = tid & 31;
    const int r0 = w * 8, c0 = l * 4;

    {
        float acc[8][4];
#pragma unroll
        for (int r = 0; r < 8; r++) { acc[r][0] = acc[r][1] = acc[r][2] = acc[r][3] = 0.f; }
#pragma unroll 4
        for (int k = 0; k < 64; k += 2) {
            float4 w0  = *(const float4*)(s_w + k * 128 + c0);
            float4 w1v = *(const float4*)(s_w + (k + 1) * 128 + c0);
#pragma unroll
            for (int r = 0; r < 8; r++) {
                float2 a = *(const float2*)(s_g1 + (r0 + r) * 64 + k);
                acc[r][0] = fmaf(a.x, w0.x, acc[r][0]); acc[r][0] = fmaf(a.y, w1v.x, acc[r][0]);
                acc[r][1] = fmaf(a.x, w0.y, acc[r][1]); acc[r][1] = fmaf(a.y, w1v.y, acc[r][1]);
                acc[r][2] = fmaf(a.x, w0.z, acc[r][2]); acc[r][2] = fmaf(a.y, w1v.z, acc[r][2]);
                acc[r][3] = fmaf(a.x, w0.w, acc[r][3]); acc[r][3] = fmaf(a.y, w1v.w, acc[r][3]);
            }
        }
#pragma unroll
        for (int r = 0; r < 8; r++) {
            float4 o;
            o.x = acc[r][0] + s_gb2[c0 + 0];
            o.y = acc[r][1] + s_gb2[c0 + 1];
            o.z = acc[r][2] + s_gb2[c0 + 2];
            o.w = acc[r][3] + s_gb2[c0 + 3];
            *(float4*)(s_x + (r0 + r) * 256 + 128 + c0) = o;
        }
    }

    float acc[8][4];
#pragma unroll
    for (int r = 0; r < 8; r++) { acc[r][0] = acc[r][1] = acc[r][2] = acc[r][3] = 0.f; }
    for (int kt = 0; kt < 4; kt++) {
        __syncthreads();
        const float4* src = (const float4*)(out_w1 + kt * 64 * 128);
        for (int i = tid; i < 2048; i += NTHREADS) ((float4*)s_w)[i] = src[i];
        __syncthreads();
#pragma unroll 4
        for (int k = 0; k < 64; k += 2) {
            float4 w0  = *(const float4*)(s_w + k * 128 + c0);
            float4 w1v = *(const float4*)(s_w + (k + 1) * 128 + c0);
#pragma unroll
            for (int r = 0; r < 8; r++) {
                float2 a = *(const float2*)(s_x + (r0 + r) * 256 + kt * 64 + k);
                acc[r][0] = fmaf(a.x, w0.x, acc[r][0]); acc[r][0] = fmaf(a.y, w1v.x, acc[r][0]);
                acc[r][1] = fmaf(a.x, w0.y, acc[r][1]); acc[r][1] = fmaf(a.y, w1v.y, acc[r][1]);
                acc[r][2] = fmaf(a.x, w0.z, acc[r][2]); acc[r][2] = fmaf(a.y, w1v.z, acc[r][2]);
                acc[r][3] = fmaf(a.x, w0.w, acc[r][3]); acc[r][3] = fmaf(a.y, w1v.w, acc[r][3]);
            }
        }
    }
#pragma unroll
    for (int r = 0; r < 8; r++) {
        float* t = s_t + (r0 + r) * 132;
        t[c0 + 0] = lrelu(acc[r][0] + s_ob1[c0 + 0]);
        t[c0 + 1] = lrelu(acc[r][1] + s_ob1[c0 + 1]);
        t[c0 + 2] = lrelu(acc[r][2] + s_ob1[c0 + 2]);
        t[c0 + 3] = lrelu(acc[r][3] + s_ob1[c0 + 3]);
    }
    __syncthreads();

    if (tid < 64) {
        float s = out_b2[0];
        const float* t = s_t + tid * 132;
#pragma unroll 8
        for (int k = 0; k < 128; k++) s = fmaf(t[k], s_ow2[k], s);
        out[row0 + tid] = s;
    }
}

// ---------------------------------------------------------------------------
extern "C" void kernel_launch(void* const* d_in, const int* in_sizes, int n_in,
                              void* d_out, int out_size)
{
    // Disambiguate input ordering via in_sizes[3] (pred=3932160 vs pi_w1=64).
    int idx_pred, idx_ispo, wbase;
    if (in_sizes[3] == (LL - 1) * PP * KK) { idx_pred = 3; idx_ispo = 4; wbase = 5; }
    else                                   { idx_pred = 23; idx_ispo = 24; wbase = 3; }
    (void)idx_ispo;

    const float* delay  = (const float*)d_in[0];
    const float* feat   = (const float*)d_in[1];
    const float* PO     = (const float*)d_in[2];
    const int*   pred   = (const int*)d_in[idx_pred];
    const float* pi_w1  = (const float*)d_in[wbase + 0];
    const float* pi_b1  = (const float*)d_in[wbase + 1];
    const float* pi_w2  = (const float*)d_in[wbase + 2];
    const float* pi_b2  = (const float*)d_in[wbase + 3];
    const float* ne_w1  = (const float*)d_in[wbase + 4];
    const float* ne_b1  = (const float*)d_in[wbase + 5];
    const float* ne_w2  = (const float*)d_in[wbase + 6];
    const float* ne_b2  = (const float*)d_in[wbase + 7];
    const float* sf_w1  = (const float*)d_in[wbase + 8];
    const float* sf_b1  = (const float*)d_in[wbase + 9];
    const float* sf_w2  = (const float*)d_in[wbase + 10];
    const float* sf_b2  = (const float*)d_in[wbase + 11];
    const float* gl_w1  = (const float*)d_in[wbase + 12];
    const float* gl_b1  = (const float*)d_in[wbase + 13];
    const float* gl_w2  = (const float*)d_in[wbase + 14];
    const float* gl_b2  = (const float*)d_in[wbase + 15];
    const float* out_w1 = (const float*)d_in[wbase + 16];
    const float* out_b1 = (const float*)d_in[wbase + 17];
    const float* out_w2 = (const float*)d_in[wbase + 18];
    const float* out_b2 = (const float*)d_in[wbase + 19];
    float* out = (float*)d_out;

    const int grid = PP / NROWS;  // 512
    const size_t sh_init  = (size_t)(64 * 64 + 64 * 128 + 128) * 4;
    // layer: nt 8192 + w1ne 8192 + w1sf 2048 + w2 8192 + ft 2048 + b1 128 + b2 128
    const size_t sh_layer = (size_t)(8192 + 8192 + 2048 + 8192 + 2048 + 128 + 128) * 4; // 115,712 B
    const size_t sh_final = (size_t)(16384 + 8192 + 8448 + 4096 + 128 + 128 + 128) * 4;

    cudaFuncSetAttribute(k_init,  cudaFuncAttributeMaxDynamicSharedMemorySize, (int)sh_init);
    cudaFuncSetAttribute(k_layer<true>,  cudaFuncAttributeMaxDynamicSharedMemorySize, (int)sh_layer);
    cudaFuncSetAttribute(k_layer<false>, cudaFuncAttributeMaxDynamicSharedMemorySize, (int)sh_layer);
    cudaFuncSetAttribute(k_final, cudaFuncAttributeMaxDynamicSharedMemorySize, (int)sh_final);

    k_init<<<grid, NTHREADS, sh_init>>>(delay, pi_w1, pi_b1, pi_w2, pi_b2);
    for (int i = 1; i < LL; i++) {
        const int* pl = pred + (long long)(i - 1) * PP * KK;
        if (i < LL - 1)
            k_layer<true><<<grid, NTHREADS, sh_layer>>>(i * PP, pl, feat,
                ne_w1, ne_b1, ne_w2, ne_b2, sf_w1, sf_b1, sf_w2, sf_b2);
        else
            k_layer<false><<<grid, NTHREADS, sh_layer>>>(i * PP, pl, feat,
                ne_w1, ne_b1, ne_w2, ne_b2, sf_w1, sf_b1, sf_w2, sf_b2);
    }
    k_final<<<grid, NTHREADS, sh_final>>>(PO, gl_w1, gl_b1, gl_w2, gl_b2,
                                          out_w1, out_b1, out_w2, out_b2, out);
}

// round 5
// speedup vs baseline: 1.4780x; 1.0053x over previous
#include <cuda_runtime.h>

#define PP 32768
#define LL 16
#define KK 8
#define HH 128
#define NROWS 64
#define NTHREADS 256

// Full h buffer for all L*P nodes (pred holds GLOBAL indices). 256 MiB static.
__device__ float g_h[(long long)LL * PP * HH];

__device__ __forceinline__ float lrelu(float x) { return x > 0.0f ? x : 0.1f * x; }
__device__ __forceinline__ float relu_(float x) { return x > 0.0f ? x : 0.0f; }

// ---------------------------------------------------------------------------
// h[0:P] = mlp2(delay, pi)
// ---------------------------------------------------------------------------
__global__ void __launch_bounds__(NTHREADS, 1)
k_init(const float* __restrict__ delay,
       const float* __restrict__ w1, const float* __restrict__ b1,
       const float* __restrict__ w2, const float* __restrict__ b2)
{
    extern __shared__ float smem[];
    float* s_t1 = smem;            // 64*64
    float* s_w2 = s_t1 + 64 * 64;  // 64*128
    float* s_b2 = s_w2 + 64 * 128; // 128

    const int tid  = threadIdx.x;
    const int row0 = blockIdx.x * NROWS;

    for (int i = tid; i < (64 * 128) / 4; i += NTHREADS)
        ((float4*)s_w2)[i] = ((const float4*)w2)[i];
    for (int i = tid; i < 128; i += NTHREADS) s_b2[i] = b2[i];
    for (int i = tid; i < 64 * 64; i += NTHREADS) {
        int r = i >> 6, c = i & 63;
        s_t1[i] = lrelu(delay[row0 + r] * w1[c] + b1[c]);
    }
    __syncthreads();

    const int w = tid >> 5, l = tid & 31;
    const int r0 = w * 8, c0 = l * 4;
    float acc[8][4];
#pragma unroll
    for (int r = 0; r < 8; r++)
#pragma unroll
        for (int c = 0; c < 4; c++) acc[r][c] = 0.0f;

#pragma unroll 4
    for (int k = 0; k < 64; k += 2) {
        float4 w0  = *(const float4*)(s_w2 + k * 128 + c0);
        float4 w1v = *(const float4*)(s_w2 + (k + 1) * 128 + c0);
#pragma unroll
        for (int r = 0; r < 8; r++) {
            float2 a = *(const float2*)(s_t1 + (r0 + r) * 64 + k);
            acc[r][0] = fmaf(a.x, w0.x, acc[r][0]); acc[r][0] = fmaf(a.y, w1v.x, acc[r][0]);
            acc[r][1] = fmaf(a.x, w0.y, acc[r][1]); acc[r][1] = fmaf(a.y, w1v.y, acc[r][1]);
            acc[r][2] = fmaf(a.x, w0.z, acc[r][2]); acc[r][2] = fmaf(a.y, w1v.z, acc[r][2]);
            acc[r][3] = fmaf(a.x, w0.w, acc[r][3]); acc[r][3] = fmaf(a.y, w1v.w, acc[r][3]);
        }
    }
#pragma unroll
    for (int r = 0; r < 8; r++) {
        float4 o;
        o.x = acc[r][0] + s_b2[c0 + 0];
        o.y = acc[r][1] + s_b2[c0 + 1];
        o.z = acc[r][2] + s_b2[c0 + 2];
        o.w = acc[r][3] + s_b2[c0 + 3];
        *(float4*)(g_h + (long long)(row0 + r0 + r) * HH + c0) = o;
    }
}

// ---------------------------------------------------------------------------
// Layer i (i=1..15). 256 thr / 64 rows, 65KB smem -> 3 blocks/SM.
// All large weights staged through one 16KB buffer in k-tiles:
//   w1ne: 2 tiles of 64k x 64c; stage-2: 4 tiles of 32k x 128c
//   (ne_w2 tiles 0-1 against t cols 0..63, sf_w2 tiles 2-3 against t cols 64..127)
// pred overlays the staging buffer during gather.
// ---------------------------------------------------------------------------
template <bool DO_RELU>
__global__ void __launch_bounds__(NTHREADS, 3)
k_layer(int lo,
        const int*   __restrict__ pred,   // this layer's slice: PP*KK
        const float* __restrict__ feat,
        const float* __restrict__ ne_w1, const float* __restrict__ ne_b1,
        const float* __restrict__ ne_w2, const float* __restrict__ ne_b2,
        const float* __restrict__ sf_w1, const float* __restrict__ sf_b1,
        const float* __restrict__ sf_w2, const float* __restrict__ sf_b2)
{
    extern __shared__ float smem[];
    float* s_nt   = smem;                 // 64*128 = 8192  (neigh, then t)
    float* s_stg  = smem + 8192;          // 4096 staging (16KB)
    float* s_ft   = smem + 12288;         // 64*32  = 2048
    float* s_w1sf = smem + 14336;         // 32*64  = 2048  [k][c]
    float* s_b1   = smem + 16384;         // 128
    float* s_b2   = smem + 16512;         // 128
    int*   s_pred = (int*)s_stg;          // 512 ints, overlay

    const int tid  = threadIdx.x;
    const int row0 = blockIdx.x * NROWS;

    // ---- preload small operands + pred ----
    for (int i = tid; i < 512; i += NTHREADS)
        ((float4*)s_w1sf)[i] = ((const float4*)sf_w1)[i];
    for (int i = tid; i < 512; i += NTHREADS) {
        int r = i >> 3, c4 = i & 7;
        ((float4*)s_ft)[i] = *((const float4*)(feat + (long long)(lo + row0 + r) * 32) + c4);
    }
    for (int i = tid; i < 512; i += NTHREADS)
        s_pred[i] = pred[(long long)row0 * KK + i];
    for (int i = tid; i < 128; i += NTHREADS) {
        s_b1[i] = (i < 64) ? ne_b1[i] : sf_b1[i - 64];
        s_b2[i] = ne_b2[i] + sf_b2[i];
    }
    __syncthreads();

    // ---- gather mean of 8 predecessor rows (warp = one h row per task) ----
#pragma unroll
    for (int j = 0; j < 8; j++) {
        int task = tid + j * NTHREADS;
        int r = task >> 5, c4 = task & 31;
        const int* pr = s_pred + r * 8;
        float x = 0.f, y = 0.f, z = 0.f, ww = 0.f;
#pragma unroll
        for (int k = 0; k < 8; k++) {
            const float4 v = *((const float4*)(g_h + (long long)pr[k] * HH) + c4);
            x += v.x; y += v.y; z += v.z; ww += v.w;
        }
        *((float4*)(s_nt + r * 128) + c4) =
            make_float4(x * 0.125f, y * 0.125f, z * 0.125f, ww * 0.125f);
    }
    __syncthreads();   // gather done; s_pred dead -> staging reusable

    const int w = tid >> 5, l = tid & 31;
    const int r0 = w * 8;
    const int cA = l * 2;

    // ---- stage 1, ne path: k=128 in two 64-k staged halves ----
    float accA[8][2];
#pragma unroll
    for (int r = 0; r < 8; r++) { accA[r][0] = 0.f; accA[r][1] = 0.f; }

#pragma unroll 1
    for (int half = 0; half < 2; half++) {
        for (int i = tid; i < 1024; i += NTHREADS)
            ((float4*)s_stg)[i] = ((const float4*)ne_w1)[half * 1024 + i];
        __syncthreads();
        const int kb = half * 64;
#pragma unroll 4
        for (int k = 0; k < 64; k += 2) {
            float2 w0  = *(const float2*)(s_stg + k * 64 + cA);
            float2 w1v = *(const float2*)(s_stg + (k + 1) * 64 + cA);
#pragma unroll
            for (int r = 0; r < 8; r++) {
                float2 a = *(const float2*)(s_nt + (r0 + r) * 128 + kb + k);
                accA[r][0] = fmaf(a.x, w0.x, accA[r][0]); accA[r][0] = fmaf(a.y, w1v.x, accA[r][0]);
                accA[r][1] = fmaf(a.x, w0.y, accA[r][1]); accA[r][1] = fmaf(a.y, w1v.y, accA[r][1]);
            }
        }
        __syncthreads();   // reads of s_stg done before next overwrite
    }

    // ---- stage 1, sf path: k=32 (resident weights) ----
    float accB[8][2];
#pragma unroll
    for (int r = 0; r < 8; r++) { accB[r][0] = 0.f; accB[r][1] = 0.f; }
#pragma unroll
    for (int k = 0; k < 32; k += 2) {
        float2 w0  = *(const float2*)(s_w1sf + k * 64 + cA);
        float2 w1v = *(const float2*)(s_w1sf + (k + 1) * 64 + cA);
#pragma unroll
        for (int r = 0; r < 8; r++) {
            float2 a = *(const float2*)(s_ft + (r0 + r) * 32 + k);
            accB[r][0] = fmaf(a.x, w0.x, accB[r][0]); accB[r][0] = fmaf(a.y, w1v.x, accB[r][0]);
            accB[r][1] = fmaf(a.x, w0.y, accB[r][1]); accB[r][1] = fmaf(a.y, w1v.y, accB[r][1]);
        }
    }

    // t overwrites s_nt (warp-own rows only): [t_ne(64) | t_sf(64)] per row
#pragma unroll
    for (int r = 0; r < 8; r++) {
        float* t = s_nt + (r0 + r) * 128;
        t[cA]          = lrelu(accA[r][0] + s_b1[cA]);
        t[cA + 1]      = lrelu(accA[r][1] + s_b1[cA + 1]);
        t[64 + cA]     = lrelu(accB[r][0] + s_b1[64 + cA]);
        t[64 + cA + 1] = lrelu(accB[r][1] + s_b1[64 + cA + 1]);
    }
    __syncthreads();

    // ---- stage 2: 4 staged tiles of 32k x 128c ----
    const int c0 = l * 4;
    float acc[8][4];
#pragma unroll
    for (int r = 0; r < 8; r++) { acc[r][0] = acc[r][1] = acc[r][2] = acc[r][3] = 0.f; }

#pragma unroll 1
    for (int j = 0; j < 4; j++) {
        const float4* src = (j < 2) ? ((const float4*)ne_w2) + j * 1024
                                    : ((const float4*)sf_w2) + (j - 2) * 1024;
        for (int i = tid; i < 1024; i += NTHREADS)
            ((float4*)s_stg)[i] = src[i];
        __syncthreads();
        const int kb = j * 32;     // t column base (ne: 0,32; sf: 64,96)
#pragma unroll 4
        for (int k = 0; k < 32; k += 2) {
            float4 w0  = *(const float4*)(s_stg + k * 128 + c0);
            float4 w1v = *(const float4*)(s_stg + (k + 1) * 128 + c0);
#pragma unroll
            for (int r = 0; r < 8; r++) {
                float2 a = *(const float2*)(s_nt + (r0 + r) * 128 + kb + k);
                acc[r][0] = fmaf(a.x, w0.x, acc[r][0]); acc[r][0] = fmaf(a.y, w1v.x, acc[r][0]);
                acc[r][1] = fmaf(a.x, w0.y, acc[r][1]); acc[r][1] = fmaf(a.y, w1v.y, acc[r][1]);
                acc[r][2] = fmaf(a.x, w0.z, acc[r][2]); acc[r][2] = fmaf(a.y, w1v.z, acc[r][2]);
                acc[r][3] = fmaf(a.x, w0.w, acc[r][3]); acc[r][3] = fmaf(a.y, w1v.w, acc[r][3]);
            }
        }
        __syncthreads();
    }

    // ---- epilogue ----
#pragma unroll
    for (int r = 0; r < 8; r++) {
        float4 o;
        o.x = acc[r][0] + s_b2[c0 + 0];
        o.y = acc[r][1] + s_b2[c0 + 1];
        o.z = acc[r][2] + s_b2[c0 + 2];
        o.w = acc[r][3] + s_b2[c0 + 3];
        if (DO_RELU) { o.x = relu_(o.x); o.y = relu_(o.y); o.z = relu_(o.z); o.w = relu_(o.w); }
        *(float4*)(g_h + (long long)(lo + row0 + r0 + r) * HH + c0) = o;
    }
}

// ---------------------------------------------------------------------------
// Final head: h_glob = mlp2(PO_feat, gl); out = mlp2([h_gnn | h_glob], out)
// ---------------------------------------------------------------------------
__global__ void __launch_bounds__(NTHREADS, 1)
k_final(const float* __restrict__ PO,
        const float* __restrict__ gl_w1, const float* __restrict__ gl_b1,
        const float* __restrict__ gl_w2, const float* __restrict__ gl_b2,
        const float* __restrict__ out_w1, const float* __restrict__ out_b1,
        const float* __restrict__ out_w2, const float* __restrict__ out_b2,
        float* __restrict__ out)
{
    extern __shared__ float smem[];
    float* s_x   = smem;             // 64*256
    float* s_w   = s_x + 16384;      // 64*128
    float* s_t   = s_w + 8192;       // 64*132
    float* s_g1  = s_t + 8448;       // 64*64
    float* s_gb2 = s_g1 + 4096;      // 128
    float* s_ob1 = s_gb2 + 128;      // 128
    float* s_ow2 = s_ob1 + 128;      // 128

    const int tid  = threadIdx.x;
    const int row0 = blockIdx.x * NROWS;
    const long long gnn0 = (long long)(LL - 1) * PP * HH;

    for (int i = tid; i < 2048; i += NTHREADS)
        ((float4*)s_w)[i] = ((const float4*)gl_w2)[i];
    for (int i = tid; i < 128; i += NTHREADS) {
        s_gb2[i] = gl_b2[i];
        s_ob1[i] = out_b1[i];
        s_ow2[i] = out_w2[i];
    }
    for (int i = tid; i < 64 * 64; i += NTHREADS) {
        int r = i >> 6, c = i & 63;
        s_g1[i] = lrelu(PO[row0 + r] * gl_w1[c] + gl_b1[c]);
    }
    for (int i = tid; i < 2048; i += NTHREADS) {
        int r = i >> 5, c4 = i & 31;
        float4 v = *((const float4*)(g_h + gnn0 + (long long)(row0 + r) * HH) + c4);
        *((float4*)(s_x + r * 256) + c4) = v;
    }
    __syncthreads();

    const int w = tid >> 5, l = tid & 31;
    const int r0 = w * 8, c0 = l * 4;

    {
        float acc[8][4];
#pragma unroll
        for (int r = 0; r < 8; r++) { acc[r][0] = acc[r][1] = acc[r][2] = acc[r][3] = 0.f; }
#pragma unroll 4
        for (int k = 0; k < 64; k += 2) {
            float4 w0  = *(const float4*)(s_w + k * 128 + c0);
            float4 w1v = *(const float4*)(s_w + (k + 1) * 128 + c0);
#pragma unroll
            for (int r = 0; r < 8; r++) {
                float2 a = *(const float2*)(s_g1 + (r0 + r) * 64 + k);
                acc[r][0] = fmaf(a.x, w0.x, acc[r][0]); acc[r][0] = fmaf(a.y, w1v.x, acc[r][0]);
                acc[r][1] = fmaf(a.x, w0.y, acc[r][1]); acc[r][1] = fmaf(a.y, w1v.y, acc[r][1]);
                acc[r][2] = fmaf(a.x, w0.z, acc[r][2]); acc[r][2] = fmaf(a.y, w1v.z, acc[r][2]);
                acc[r][3] = fmaf(a.x, w0.w, acc[r][3]); acc[r][3] = fmaf(a.y, w1v.w, acc[r][3]);
            }
        }
#pragma unroll
        for (int r = 0; r < 8; r++) {
            float4 o;
            o.x = acc[r][0] + s_gb2[c0 + 0];
            o.y = acc[r][1] + s_gb2[c0 + 1];
            o.z = acc[r][2] + s_gb2[c0 + 2];
            o.w = acc[r][3] + s_gb2[c0 + 3];
            *(float4*)(s_x + (r0 + r) * 256 + 128 + c0) = o;
        }
    }

    float acc[8][4];
#pragma unroll
    for (int r = 0; r < 8; r++) { acc[r][0] = acc[r][1] = acc[r][2] = acc[r][3] = 0.f; }
    for (int kt = 0; kt < 4; kt++) {
        __syncthreads();
        const float4* src = (const float4*)(out_w1 + kt * 64 * 128);
        for (int i = tid; i < 2048; i += NTHREADS) ((float4*)s_w)[i] = src[i];
        __syncthreads();
#pragma unroll 4
        for (int k = 0; k < 64; k += 2) {
            float4 w0  = *(const float4*)(s_w + k * 128 + c0);
            float4 w1v = *(const float4*)(s_w + (k + 1) * 128 + c0);
#pragma unroll
            for (int r = 0; r < 8; r++) {
                float2 a = *(const float2*)(s_x + (r0 + r) * 256 + kt * 64 + k);
                acc[r][0] = fmaf(a.x, w0.x, acc[r][0]); acc[r][0] = fmaf(a.y, w1v.x, acc[r][0]);
                acc[r][1] = fmaf(a.x, w0.y, acc[r][1]); acc[r][1] = fmaf(a.y, w1v.y, acc[r][1]);
                acc[r][2] = fmaf(a.x, w0.z, acc[r][2]); acc[r][2] = fmaf(a.y, w1v.z, acc[r][2]);
                acc[r][3] = fmaf(a.x, w0.w, acc[r][3]); acc[r][3] = fmaf(a.y, w1v.w, acc[r][3]);
            }
        }
    }
#pragma unroll
    for (int r = 0; r < 8; r++) {
        float* t = s_t + (r0 + r) * 132;
        t[c0 + 0] = lrelu(acc[r][0] + s_ob1[c0 + 0]);
        t[c0 + 1] = lrelu(acc[r][1] + s_ob1[c0 + 1]);
        t[c0 + 2] = lrelu(acc[r][2] + s_ob1[c0 + 2]);
        t[c0 + 3] = lrelu(acc[r][3] + s_ob1[c0 + 3]);
    }
    __syncthreads();

    if (tid < 64) {
        float s = out_b2[0];
        const float* t = s_t + tid * 132;
#pragma unroll 8
        for (int k = 0; k < 128; k++) s = fmaf(t[k], s_ow2[k], s);
        out[row0 + tid] = s;
    }
}

// ---------------------------------------------------------------------------
extern "C" void kernel_launch(void* const* d_in, const int* in_sizes, int n_in,
                              void* d_out, int out_size)
{
    // Disambiguate input ordering via in_sizes[3] (pred=3932160 vs pi_w1=64).
    int idx_pred, idx_ispo, wbase;
    if (in_sizes[3] == (LL - 1) * PP * KK) { idx_pred = 3; idx_ispo = 4; wbase = 5; }
    else                                   { idx_pred = 23; idx_ispo = 24; wbase = 3; }
    (void)idx_ispo;

    const float* delay  = (const float*)d_in[0];
    const float* feat   = (const float*)d_in[1];
    const float* PO     = (const float*)d_in[2];
    const int*   pred   = (const int*)d_in[idx_pred];
    const float* pi_w1  = (const float*)d_in[wbase + 0];
    const float* pi_b1  = (const float*)d_in[wbase + 1];
    const float* pi_w2  = (const float*)d_in[wbase + 2];
    const float* pi_b2  = (const float*)d_in[wbase + 3];
    const float* ne_w1  = (const float*)d_in[wbase + 4];
    const float* ne_b1  = (const float*)d_in[wbase + 5];
    const float* ne_w2  = (const float*)d_in[wbase + 6];
    const float* ne_b2  = (const float*)d_in[wbase + 7];
    const float* sf_w1  = (const float*)d_in[wbase + 8];
    const float* sf_b1  = (const float*)d_in[wbase + 9];
    const float* sf_w2  = (const float*)d_in[wbase + 10];
    const float* sf_b2  = (const float*)d_in[wbase + 11];
    const float* gl_w1  = (const float*)d_in[wbase + 12];
    const float* gl_b1  = (const float*)d_in[wbase + 13];
    const float* gl_w2  = (const float*)d_in[wbase + 14];
    const float* gl_b2  = (const float*)d_in[wbase + 15];
    const float* out_w1 = (const float*)d_in[wbase + 16];
    const float* out_b1 = (const float*)d_in[wbase + 17];
    const float* out_w2 = (const float*)d_in[wbase + 18];
    const float* out_b2 = (const float*)d_in[wbase + 19];
    float* out = (float*)d_out;

    const int grid = PP / NROWS;  // 512
    const size_t sh_init  = (size_t)(64 * 64 + 64 * 128 + 128) * 4;
    // layer: nt 8192 + stg 4096 + ft 2048 + w1sf 2048 + b1 128 + b2 128 = 16640 floats
    const size_t sh_layer = (size_t)16640 * 4;   // 66,560 B -> 3 blocks/SM
    const size_t sh_final = (size_t)(16384 + 8192 + 8448 + 4096 + 128 + 128 + 128) * 4;

    cudaFuncSetAttribute(k_init,  cudaFuncAttributeMaxDynamicSharedMemorySize, (int)sh_init);
    cudaFuncSetAttribute(k_layer<true>,  cudaFuncAttributeMaxDynamicSharedMemorySize, (int)sh_layer);
    cudaFuncSetAttribute(k_layer<false>, cudaFuncAttributeMaxDynamicSharedMemorySize, (int)sh_layer);
    cudaFuncSetAttribute(k_final, cudaFuncAttributeMaxDynamicSharedMemorySize, (int)sh_final);

    k_init<<<grid, NTHREADS, sh_init>>>(delay, pi_w1, pi_b1, pi_w2, pi_b2);
    for (int i = 1; i < LL; i++) {
        const int* pl = pred + (long long)(i - 1) * PP * KK;
        if (i < LL - 1)
            k_layer<true><<<grid, NTHREADS, sh_layer>>>(i * PP, pl, feat,
                ne_w1, ne_b1, ne_w2, ne_b2, sf_w1, sf_b1, sf_w2, sf_b2);
        else
            k_layer<false><<<grid, NTHREADS, sh_layer>>>(i * PP, pl, feat,
                ne_w1, ne_b1, ne_w2, ne_b2, sf_w1, sf_b1, sf_w2, sf_b2);
    }
    k_final<<<grid, NTHREADS, sh_final>>>(PO, gl_w1, gl_b1, gl_w2, gl_b2,
                                          out_w1, out_b1, out_w2, out_b2, out);
}

// round 6
// speedup vs baseline: 1.6082x; 1.0880x over previous
#include <cuda_runtime.h>

#define PP 32768
#define LL 16
#define KK 8
#define HH 128

// Full h buffer for all L*P nodes (pred holds GLOBAL indices). 256 MiB static.
__device__ float g_h[(long long)LL * PP * HH];

__device__ __forceinline__ float lrelu(float x) { return x > 0.0f ? x : 0.1f * x; }
__device__ __forceinline__ float relu_(float x) { return x > 0.0f ? x : 0.0f; }

// ---------------------------------------------------------------------------
// h[0:P] = mlp2(delay, pi)   (unchanged; ~1us)
// ---------------------------------------------------------------------------
__global__ void __launch_bounds__(256, 1)
k_init(const float* __restrict__ delay,
       const float* __restrict__ w1, const float* __restrict__ b1,
       const float* __restrict__ w2, const float* __restrict__ b2)
{
    extern __shared__ float smem[];
    float* s_t1 = smem;            // 64*64
    float* s_w2 = s_t1 + 64 * 64;  // 64*128
    float* s_b2 = s_w2 + 64 * 128; // 128

    const int tid  = threadIdx.x;
    const int row0 = blockIdx.x * 64;

    for (int i = tid; i < (64 * 128) / 4; i += 256)
        ((float4*)s_w2)[i] = ((const float4*)w2)[i];
    for (int i = tid; i < 128; i += 256) s_b2[i] = b2[i];
    for (int i = tid; i < 64 * 64; i += 256) {
        int r = i >> 6, c = i & 63;
        s_t1[i] = lrelu(delay[row0 + r] * w1[c] + b1[c]);
    }
    __syncthreads();

    const int w = tid >> 5, l = tid & 31;
    const int r0 = w * 8, c0 = l * 4;
    float acc[8][4];
#pragma unroll
    for (int r = 0; r < 8; r++)
#pragma unroll
        for (int c = 0; c < 4; c++) acc[r][c] = 0.0f;

#pragma unroll 4
    for (int k = 0; k < 64; k += 2) {
        float4 w0  = *(const float4*)(s_w2 + k * 128 + c0);
        float4 w1v = *(const float4*)(s_w2 + (k + 1) * 128 + c0);
#pragma unroll
        for (int r = 0; r < 8; r++) {
            float2 a = *(const float2*)(s_t1 + (r0 + r) * 64 + k);
            acc[r][0] = fmaf(a.x, w0.x, acc[r][0]); acc[r][0] = fmaf(a.y, w1v.x, acc[r][0]);
            acc[r][1] = fmaf(a.x, w0.y, acc[r][1]); acc[r][1] = fmaf(a.y, w1v.y, acc[r][1]);
            acc[r][2] = fmaf(a.x, w0.z, acc[r][2]); acc[r][2] = fmaf(a.y, w1v.z, acc[r][2]);
            acc[r][3] = fmaf(a.x, w0.w, acc[r][3]); acc[r][3] = fmaf(a.y, w1v.w, acc[r][3]);
        }
    }
#pragma unroll
    for (int r = 0; r < 8; r++) {
        float4 o;
        o.x = acc[r][0] + s_b2[c0 + 0];
        o.y = acc[r][1] + s_b2[c0 + 1];
        o.z = acc[r][2] + s_b2[c0 + 2];
        o.w = acc[r][3] + s_b2[c0 + 3];
        *(float4*)(g_h + (long long)(row0 + r0 + r) * HH + c0) = o;
    }
}

// ---------------------------------------------------------------------------
// Layer i (i=1..15). 128 thr / 32 rows / block, 29.7KB smem -> 7 blocks/SM.
// grid = 1024 <= 148*7 = 1036 -> single wave.
// All weights staged through one 8KB buffer (13 k-tiles). float4 k-stepping.
// ---------------------------------------------------------------------------
template <bool DO_RELU>
__global__ void __launch_bounds__(128, 7)
k_layer(int lo,
        const int*   __restrict__ pred,   // this layer's slice: PP*KK
        const float* __restrict__ feat,
        const float* __restrict__ ne_w1, const float* __restrict__ ne_b1,
        const float* __restrict__ ne_w2, const float* __restrict__ ne_b2,
        const float* __restrict__ sf_w1, const float* __restrict__ sf_b1,
        const float* __restrict__ sf_w2, const float* __restrict__ sf_b2)
{
    extern __shared__ float smem[];
    float* s_nt  = smem;            // 32*128 = 4096 floats (neigh, then t)
    float* s_stg = smem + 4096;     // 2048 floats staging (8KB)
    float* s_ft  = smem + 6144;     // 32*32 = 1024
    float* s_b1  = smem + 7168;     // 128
    float* s_b2  = smem + 7296;     // 128
    int*   s_pred = (int*)s_stg;    // 256 ints, overlay

    const int tid  = threadIdx.x;
    const int row0 = blockIdx.x * 32;

    // ---- preload ft, pred, biases ----
    for (int i = tid; i < 256; i += 128) {
        int r = i >> 3, c4 = i & 7;
        ((float4*)(s_ft + r * 32))[c4] =
            *((const float4*)(feat + (long long)(lo + row0 + r) * 32) + c4);
    }
    for (int i = tid; i < 256; i += 128)
        s_pred[i] = pred[(long long)row0 * KK + i];
    if (tid < 128) {
        s_b1[tid] = (tid < 64) ? ne_b1[tid] : sf_b1[tid - 64];
        s_b2[tid] = ne_b2[tid] + sf_b2[tid];
    }
    __syncthreads();

    // ---- gather mean of 8 predecessor rows (warp = one h row per task) ----
#pragma unroll
    for (int j = 0; j < 8; j++) {
        int task = tid + j * 128;
        int r = task >> 5, c4 = task & 31;
        const int* pr = s_pred + r * 8;
        float x = 0.f, y = 0.f, z = 0.f, ww = 0.f;
#pragma unroll
        for (int k = 0; k < 8; k++) {
            const float4 v = *((const float4*)(g_h + (long long)pr[k] * HH) + c4);
            x += v.x; y += v.y; z += v.z; ww += v.w;
        }
        *((float4*)(s_nt + r * 128) + c4) =
            make_float4(x * 0.125f, y * 0.125f, z * 0.125f, ww * 0.125f);
    }
    __syncthreads();   // gather done; s_pred dead -> staging reusable

    const int w = tid >> 5, l = tid & 31;     // 4 warps; warp owns 8 rows
    const int r0 = w * 8;
    // stage-1 mapping: half-warp = 4 rows, (l&15)*4 = 4 cols
    const int rsub = l >> 4;
    const int r1 = r0 + rsub * 4;
    const int cg = (l & 15) * 4;

    // ---- stage 1, ne path: k=128 in four 32-k tiles (32k x 64c = 8KB) ----
    float accA[4][4];
#pragma unroll
    for (int i = 0; i < 4; i++)
#pragma unroll
        for (int c = 0; c < 4; c++) accA[i][c] = 0.f;

#pragma unroll 1
    for (int kt = 0; kt < 4; kt++) {
        for (int i = tid; i < 512; i += 128)
            ((float4*)s_stg)[i] = ((const float4*)ne_w1)[kt * 512 + i];
        __syncthreads();
        const int kb = kt * 32;
#pragma unroll 2
        for (int k = 0; k < 32; k += 4) {
            float4 wv0 = *(const float4*)(s_stg + (k + 0) * 64 + cg);
            float4 wv1 = *(const float4*)(s_stg + (k + 1) * 64 + cg);
            float4 wv2 = *(const float4*)(s_stg + (k + 2) * 64 + cg);
            float4 wv3 = *(const float4*)(s_stg + (k + 3) * 64 + cg);
#pragma unroll
            for (int i = 0; i < 4; i++) {
                float4 a = *(const float4*)(s_nt + (r1 + i) * 128 + kb + k);
                accA[i][0] = fmaf(a.x, wv0.x, accA[i][0]); accA[i][0] = fmaf(a.y, wv1.x, accA[i][0]);
                accA[i][0] = fmaf(a.z, wv2.x, accA[i][0]); accA[i][0] = fmaf(a.w, wv3.x, accA[i][0]);
                accA[i][1] = fmaf(a.x, wv0.y, accA[i][1]); accA[i][1] = fmaf(a.y, wv1.y, accA[i][1]);
                accA[i][1] = fmaf(a.z, wv2.y, accA[i][1]); accA[i][1] = fmaf(a.w, wv3.y, accA[i][1]);
                accA[i][2] = fmaf(a.x, wv0.z, accA[i][2]); accA[i][2] = fmaf(a.y, wv1.z, accA[i][2]);
                accA[i][2] = fmaf(a.z, wv2.z, accA[i][2]); accA[i][2] = fmaf(a.w, wv3.z, accA[i][2]);
                accA[i][3] = fmaf(a.x, wv0.w, accA[i][3]); accA[i][3] = fmaf(a.y, wv1.w, accA[i][3]);
                accA[i][3] = fmaf(a.z, wv2.w, accA[i][3]); accA[i][3] = fmaf(a.w, wv3.w, accA[i][3]);
            }
        }
        __syncthreads();   // stg reads done before next tile's overwrite
    }

    // t_ne overwrites s_nt cols [cg, cg+4) of own 4 rows (all reads done at sync)
#pragma unroll
    for (int i = 0; i < 4; i++) {
        float4 o;
        o.x = lrelu(accA[i][0] + s_b1[cg + 0]);
        o.y = lrelu(accA[i][1] + s_b1[cg + 1]);
        o.z = lrelu(accA[i][2] + s_b1[cg + 2]);
        o.w = lrelu(accA[i][3] + s_b1[cg + 3]);
        *(float4*)(s_nt + (r1 + i) * 128 + cg) = o;
    }

    // ---- stage 1, sf path: one tile (32k x 64c) ----
    float accB[4][4];
#pragma unroll
    for (int i = 0; i < 4; i++)
#pragma unroll
        for (int c = 0; c < 4; c++) accB[i][c] = 0.f;

    for (int i = tid; i < 512; i += 128)
        ((float4*)s_stg)[i] = ((const float4*)sf_w1)[i];
    __syncthreads();
#pragma unroll 2
    for (int k = 0; k < 32; k += 4) {
        float4 wv0 = *(const float4*)(s_stg + (k + 0) * 64 + cg);
        float4 wv1 = *(const float4*)(s_stg + (k + 1) * 64 + cg);
        float4 wv2 = *(const float4*)(s_stg + (k + 2) * 64 + cg);
        float4 wv3 = *(const float4*)(s_stg + (k + 3) * 64 + cg);
#pragma unroll
        for (int i = 0; i < 4; i++) {
            float4 a = *(const float4*)(s_ft + (r1 + i) * 32 + k);
            accB[i][0] = fmaf(a.x, wv0.x, accB[i][0]); accB[i][0] = fmaf(a.y, wv1.x, accB[i][0]);
            accB[i][0] = fmaf(a.z, wv2.x, accB[i][0]); accB[i][0] = fmaf(a.w, wv3.x, accB[i][0]);
            accB[i][1] = fmaf(a.x, wv0.y, accB[i][1]); accB[i][1] = fmaf(a.y, wv1.y, accB[i][1]);
            accB[i][1] = fmaf(a.z, wv2.y, accB[i][1]); accB[i][1] = fmaf(a.w, wv3.y, accB[i][1]);
            accB[i][2] = fmaf(a.x, wv0.z, accB[i][2]); accB[i][2] = fmaf(a.y, wv1.z, accB[i][2]);
            accB[i][2] = fmaf(a.z, wv2.z, accB[i][2]); accB[i][2] = fmaf(a.w, wv3.z, accB[i][2]);
            accB[i][3] = fmaf(a.x, wv0.w, accB[i][3]); accB[i][3] = fmaf(a.y, wv1.w, accB[i][3]);
            accB[i][3] = fmaf(a.z, wv2.w, accB[i][3]); accB[i][3] = fmaf(a.w, wv3.w, accB[i][3]);
        }
    }
    // t_sf: cols [64+cg, 64+cg+4) of own 4 rows
#pragma unroll
    for (int i = 0; i < 4; i++) {
        float4 o;
        o.x = lrelu(accB[i][0] + s_b1[64 + cg + 0]);
        o.y = lrelu(accB[i][1] + s_b1[64 + cg + 1]);
        o.z = lrelu(accB[i][2] + s_b1[64 + cg + 2]);
        o.w = lrelu(accB[i][3] + s_b1[64 + cg + 3]);
        *(float4*)(s_nt + (r1 + i) * 128 + 64 + cg) = o;
    }
    __syncthreads();   // sf-stg reads + all t writes complete

    // ---- stage 2: 8 tiles of 16k x 128c (8KB each) ----
    const int c0 = l * 4;
    float acc[8][4];
#pragma unroll
    for (int r = 0; r < 8; r++) { acc[r][0] = acc[r][1] = acc[r][2] = acc[r][3] = 0.f; }

#pragma unroll 1
    for (int j = 0; j < 8; j++) {
        const float4* src = (j < 4) ? ((const float4*)ne_w2) + j * 512
                                    : ((const float4*)sf_w2) + (j - 4) * 512;
        for (int i = tid; i < 512; i += 128)
            ((float4*)s_stg)[i] = src[i];
        __syncthreads();
        const int kb = j * 16;   // t column base
#pragma unroll 2
        for (int k = 0; k < 16; k += 4) {
            float4 wv0 = *(const float4*)(s_stg + (k + 0) * 128 + c0);
            float4 wv1 = *(const float4*)(s_stg + (k + 1) * 128 + c0);
            float4 wv2 = *(const float4*)(s_stg + (k + 2) * 128 + c0);
            float4 wv3 = *(const float4*)(s_stg + (k + 3) * 128 + c0);
#pragma unroll
            for (int r = 0; r < 8; r++) {
                float4 a = *(const float4*)(s_nt + (r0 + r) * 128 + kb + k);
                acc[r][0] = fmaf(a.x, wv0.x, acc[r][0]); acc[r][0] = fmaf(a.y, wv1.x, acc[r][0]);
                acc[r][0] = fmaf(a.z, wv2.x, acc[r][0]); acc[r][0] = fmaf(a.w, wv3.x, acc[r][0]);
                acc[r][1] = fmaf(a.x, wv0.y, acc[r][1]); acc[r][1] = fmaf(a.y, wv1.y, acc[r][1]);
                acc[r][1] = fmaf(a.z, wv2.y, acc[r][1]); acc[r][1] = fmaf(a.w, wv3.y, acc[r][1]);
                acc[r][2] = fmaf(a.x, wv0.z, acc[r][2]); acc[r][2] = fmaf(a.y, wv1.z, acc[r][2]);
                acc[r][2] = fmaf(a.z, wv2.z, acc[r][2]); acc[r][2] = fmaf(a.w, wv3.z, acc[r][2]);
                acc[r][3] = fmaf(a.x, wv0.w, acc[r][3]); acc[r][3] = fmaf(a.y, wv1.w, acc[r][3]);
                acc[r][3] = fmaf(a.z, wv2.w, acc[r][3]); acc[r][3] = fmaf(a.w, wv3.w, acc[r][3]);
            }
        }
        __syncthreads();
    }

    // ---- epilogue ----
#pragma unroll
    for (int r = 0; r < 8; r++) {
        float4 o;
        o.x = acc[r][0] + s_b2[c0 + 0];
        o.y = acc[r][1] + s_b2[c0 + 1];
        o.z = acc[r][2] + s_b2[c0 + 2];
        o.w = acc[r][3] + s_b2[c0 + 3];
        if (DO_RELU) { o.x = relu_(o.x); o.y = relu_(o.y); o.z = relu_(o.z); o.w = relu_(o.w); }
        *(float4*)(g_h + (long long)(lo + row0 + r0 + r) * HH + c0) = o;
    }
}

// ---------------------------------------------------------------------------
// Final head (unchanged)
// ---------------------------------------------------------------------------
__global__ void __launch_bounds__(256, 1)
k_final(const float* __restrict__ PO,
        const float* __restrict__ gl_w1, const float* __restrict__ gl_b1,
        const float* __restrict__ gl_w2, const float* __restrict__ gl_b2,
        const float* __restrict__ out_w1, const float* __restrict__ out_b1,
        const float* __restrict__ out_w2, const float* __restrict__ out_b2,
        float* __restrict__ out)
{
    extern __shared__ float smem[];
    float* s_x   = smem;             // 64*256
    float* s_w   = s_x + 16384;      // 64*128
    float* s_t   = s_w + 8192;       // 64*132
    float* s_g1  = s_t + 8448;       // 64*64
    float* s_gb2 = s_g1 + 4096;      // 128
    float* s_ob1 = s_gb2 + 128;      // 128
    float* s_ow2 = s_ob1 + 128;      // 128

    const int tid  = threadIdx.x;
    const int row0 = blockIdx.x * 64;
    const long long gnn0 = (long long)(LL - 1) * PP * HH;

    for (int i = tid; i < 2048; i += 256)
        ((float4*)s_w)[i] = ((const float4*)gl_w2)[i];
    for (int i = tid; i < 128; i += 256) {
        s_gb2[i] = gl_b2[i];
        s_ob1[i] = out_b1[i];
        s_ow2[i] = out_w2[i];
    }
    for (int i = tid; i < 64 * 64; i += 256) {
        int r = i >> 6, c = i & 63;
        s_g1[i] = lrelu(PO[row0 + r] * gl_w1[c] + gl_b1[c]);
    }
    for (int i = tid; i < 2048; i += 256) {
        int r = i >> 5, c4 = i & 31;
        float4 v = *((const float4*)(g_h + gnn0 + (long long)(row0 + r) * HH) + c4);
        *((float4*)(s_x + r * 256) + c4) = v;
    }
    __syncthreads();

    const int w = tid >> 5, l = tid & 31;
    const int r0 = w * 8, c0 = l * 4;

    {
        float acc[8][4];
#pragma unroll
        for (int r = 0; r < 8; r++) { acc[r][0] = acc[r][1] = acc[r][2] = acc[r][3] = 0.f; }
#pragma unroll 4
        for (int k = 0; k < 64; k += 2) {
            float4 w0  = *(const float4*)(s_w + k * 128 + c0);
            float4 w1v = *(const float4*)(s_w + (k + 1) * 128 + c0);
#pragma unroll
            for (int r = 0; r < 8; r++) {
                float2 a = *(const float2*)(s_g1 + (r0 + r) * 64 + k);
                acc[r][0] = fmaf(a.x, w0.x, acc[r][0]); acc[r][0] = fmaf(a.y, w1v.x, acc[r][0]);
                acc[r][1] = fmaf(a.x, w0.y, acc[r][1]); acc[r][1] = fmaf(a.y, w1v.y, acc[r][1]);
                acc[r][2] = fmaf(a.x, w0.z, acc[r][2]); acc[r][2] = fmaf(a.y, w1v.z, acc[r][2]);
                acc[r][3] = fmaf(a.x, w0.w, acc[r][3]); acc[r][3] = fmaf(a.y, w1v.w, acc[r][3]);
            }
        }
#pragma unroll
        for (int r = 0; r < 8; r++) {
            float4 o;
            o.x = acc[r][0] + s_gb2[c0 + 0];
            o.y = acc[r][1] + s_gb2[c0 + 1];
            o.z = acc[r][2] + s_gb2[c0 + 2];
            o.w = acc[r][3] + s_gb2[c0 + 3];
            *(float4*)(s_x + (r0 + r) * 256 + 128 + c0) = o;
        }
    }

    float acc[8][4];
#pragma unroll
    for (int r = 0; r < 8; r++) { acc[r][0] = acc[r][1] = acc[r][2] = acc[r][3] = 0.f; }
    for (int kt = 0; kt < 4; kt++) {
        __syncthreads();
        const float4* src = (const float4*)(out_w1 + kt * 64 * 128);
        for (int i = tid; i < 2048; i += 256) ((float4*)s_w)[i] = src[i];
        __syncthreads();
#pragma unroll 4
        for (int k = 0; k < 64; k += 2) {
            float4 w0  = *(const float4*)(s_w + k * 128 + c0);
            float4 w1v = *(const float4*)(s_w + (k + 1) * 128 + c0);
#pragma unroll
            for (int r = 0; r < 8; r++) {
                float2 a = *(const float2*)(s_x + (r0 + r) * 256 + kt * 64 + k);
                acc[r][0] = fmaf(a.x, w0.x, acc[r][0]); acc[r][0] = fmaf(a.y, w1v.x, acc[r][0]);
                acc[r][1] = fmaf(a.x, w0.y, acc[r][1]); acc[r][1] = fmaf(a.y, w1v.y, acc[r][1]);
                acc[r][2] = fmaf(a.x, w0.z, acc[r][2]); acc[r][2] = fmaf(a.y, w1v.z, acc[r][2]);
                acc[r][3] = fmaf(a.x, w0.w, acc[r][3]); acc[r][3] = fmaf(a.y, w1v.w, acc[r][3]);
            }
        }
    }
#pragma unroll
    for (int r = 0; r < 8; r++) {
        float* t = s_t + (r0 + r) * 132;
        t[c0 + 0] = lrelu(acc[r][0] + s_ob1[c0 + 0]);
        t[c0 + 1] = lrelu(acc[r][1] + s_ob1[c0 + 1]);
        t[c0 + 2] = lrelu(acc[r][2] + s_ob1[c0 + 2]);
        t[c0 + 3] = lrelu(acc[r][3] + s_ob1[c0 + 3]);
    }
    __syncthreads();

    if (tid < 64) {
        float s = out_b2[0];
        const float* t = s_t + tid * 132;
#pragma unroll 8
        for (int k = 0; k < 128; k++) s = fmaf(t[k], s_ow2[k], s);
        out[row0 + tid] = s;
    }
}

// ---------------------------------------------------------------------------
extern "C" void kernel_launch(void* const* d_in, const int* in_sizes, int n_in,
                              void* d_out, int out_size)
{
    // Disambiguate input ordering via in_sizes[3] (pred=3932160 vs pi_w1=64).
    int idx_pred, idx_ispo, wbase;
    if (in_sizes[3] == (LL - 1) * PP * KK) { idx_pred = 3; idx_ispo = 4; wbase = 5; }
    else                                   { idx_pred = 23; idx_ispo = 24; wbase = 3; }
    (void)idx_ispo;

    const float* delay  = (const float*)d_in[0];
    const float* feat   = (const float*)d_in[1];
    const float* PO     = (const float*)d_in[2];
    const int*   pred   = (const int*)d_in[idx_pred];
    const float* pi_w1  = (const float*)d_in[wbase + 0];
    const float* pi_b1  = (const float*)d_in[wbase + 1];
    const float* pi_w2  = (const float*)d_in[wbase + 2];
    const float* pi_b2  = (const float*)d_in[wbase + 3];
    const float* ne_w1  = (const float*)d_in[wbase + 4];
    const float* ne_b1  = (const float*)d_in[wbase + 5];
    const float* ne_w2  = (const float*)d_in[wbase + 6];
    const float* ne_b2  = (const float*)d_in[wbase + 7];
    const float* sf_w1  = (const float*)d_in[wbase + 8];
    const float* sf_b1  = (const float*)d_in[wbase + 9];
    const float* sf_w2  = (const float*)d_in[wbase + 10];
    const float* sf_b2  = (const float*)d_in[wbase + 11];
    const float* gl_w1  = (const float*)d_in[wbase + 12];
    const float* gl_b1  = (const float*)d_in[wbase + 13];
    const float* gl_w2  = (const float*)d_in[wbase + 14];
    const float* gl_b2  = (const float*)d_in[wbase + 15];
    const float* out_w1 = (const float*)d_in[wbase + 16];
    const float* out_b1 = (const float*)d_in[wbase + 17];
    const float* out_w2 = (const float*)d_in[wbase + 18];
    const float* out_b2 = (const float*)d_in[wbase + 19];
    float* out = (float*)d_out;

    const size_t sh_init  = (size_t)(64 * 64 + 64 * 128 + 128) * 4;
    // layer: nt 4096 + stg 2048 + ft 1024 + b1 128 + b2 128 = 7424 floats = 29,696B
    const size_t sh_layer = (size_t)7424 * 4;
    const size_t sh_final = (size_t)(16384 + 8192 + 8448 + 4096 + 128 + 128 + 128) * 4;

    cudaFuncSetAttribute(k_init,  cudaFuncAttributeMaxDynamicSharedMemorySize, (int)sh_init);
    cudaFuncSetAttribute(k_layer<true>,  cudaFuncAttributeMaxDynamicSharedMemorySize, (int)sh_layer);
    cudaFuncSetAttribute(k_layer<false>, cudaFuncAttributeMaxDynamicSharedMemorySize, (int)sh_layer);
    cudaFuncSetAttribute(k_final, cudaFuncAttributeMaxDynamicSharedMemorySize, (int)sh_final);

    k_init<<<PP / 64, 256, sh_init>>>(delay, pi_w1, pi_b1, pi_w2, pi_b2);
    for (int i = 1; i < LL; i++) {
        const int* pl = pred + (long long)(i - 1) * PP * KK;
        if (i < LL - 1)
            k_layer<true><<<PP / 32, 128, sh_layer>>>(i * PP, pl, feat,
                ne_w1, ne_b1, ne_w2, ne_b2, sf_w1, sf_b1, sf_w2, sf_b2);
        else
            k_layer<false><<<PP / 32, 128, sh_layer>>>(i * PP, pl, feat,
                ne_w1, ne_b1, ne_w2, ne_b2, sf_w1, sf_b1, sf_w2, sf_b2);
    }
    k_final<<<PP / 64, 256, sh_final>>>(PO, gl_w1, gl_b1, gl_w2, gl_b2,
                                        out_w1, out_b1, out_w2, out_b2, out);
}

// round 7
// speedup vs baseline: 1.8313x; 1.1388x over previous
#include <cuda_runtime.h>

#define PP 32768
#define LL 16
#define KK 8
#define HH 128

// Full h buffer for all L*P nodes (pred holds GLOBAL indices). 256 MiB static.
__device__ float g_h[(long long)LL * PP * HH];

__device__ __forceinline__ float lrelu(float x) { return x > 0.0f ? x : 0.1f * x; }
__device__ __forceinline__ float relu_(float x) { return x > 0.0f ? x : 0.0f; }

// ---------------------------------------------------------------------------
// h[0:P] = mlp2(delay, pi)   (unchanged; ~1us)
// ---------------------------------------------------------------------------
__global__ void __launch_bounds__(256, 1)
k_init(const float* __restrict__ delay,
       const float* __restrict__ w1, const float* __restrict__ b1,
       const float* __restrict__ w2, const float* __restrict__ b2)
{
    extern __shared__ float smem[];
    float* s_t1 = smem;            // 64*64
    float* s_w2 = s_t1 + 64 * 64;  // 64*128
    float* s_b2 = s_w2 + 64 * 128; // 128

    const int tid  = threadIdx.x;
    const int row0 = blockIdx.x * 64;

    for (int i = tid; i < (64 * 128) / 4; i += 256)
        ((float4*)s_w2)[i] = ((const float4*)w2)[i];
    for (int i = tid; i < 128; i += 256) s_b2[i] = b2[i];
    for (int i = tid; i < 64 * 64; i += 256) {
        int r = i >> 6, c = i & 63;
        s_t1[i] = lrelu(delay[row0 + r] * w1[c] + b1[c]);
    }
    __syncthreads();

    const int w = tid >> 5, l = tid & 31;
    const int r0 = w * 8, c0 = l * 4;
    float acc[8][4];
#pragma unroll
    for (int r = 0; r < 8; r++)
#pragma unroll
        for (int c = 0; c < 4; c++) acc[r][c] = 0.0f;

#pragma unroll 4
    for (int k = 0; k < 64; k += 2) {
        float4 w0  = *(const float4*)(s_w2 + k * 128 + c0);
        float4 w1v = *(const float4*)(s_w2 + (k + 1) * 128 + c0);
#pragma unroll
        for (int r = 0; r < 8; r++) {
            float2 a = *(const float2*)(s_t1 + (r0 + r) * 64 + k);
            acc[r][0] = fmaf(a.x, w0.x, acc[r][0]); acc[r][0] = fmaf(a.y, w1v.x, acc[r][0]);
            acc[r][1] = fmaf(a.x, w0.y, acc[r][1]); acc[r][1] = fmaf(a.y, w1v.y, acc[r][1]);
            acc[r][2] = fmaf(a.x, w0.z, acc[r][2]); acc[r][2] = fmaf(a.y, w1v.z, acc[r][2]);
            acc[r][3] = fmaf(a.x, w0.w, acc[r][3]); acc[r][3] = fmaf(a.y, w1v.w, acc[r][3]);
        }
    }
#pragma unroll
    for (int r = 0; r < 8; r++) {
        float4 o;
        o.x = acc[r][0] + s_b2[c0 + 0];
        o.y = acc[r][1] + s_b2[c0 + 1];
        o.z = acc[r][2] + s_b2[c0 + 2];
        o.w = acc[r][3] + s_b2[c0 + 3];
        *(float4*)(g_h + (long long)(row0 + r0 + r) * HH + c0) = o;
    }
}

// ---------------------------------------------------------------------------
// Layer i (i=1..15). 128 thr / 32 rows / block, 22.5KB smem, 7 blocks/SM.
// grid = 1024 <= 148*7 -> single wave.
// Weights are read DIRECTLY from global (L1/L2-resident, coalesced float4)
// inside the FMA loops — no staging, no block syncs after the gather.
// ---------------------------------------------------------------------------
template <bool DO_RELU>
__global__ void __launch_bounds__(128, 7)
k_layer(int lo,
        const int*   __restrict__ pred,   // this layer's slice: PP*KK
        const float* __restrict__ feat,
        const float* __restrict__ ne_w1, const float* __restrict__ ne_b1,
        const float* __restrict__ ne_w2, const float* __restrict__ ne_b2,
        const float* __restrict__ sf_w1, const float* __restrict__ sf_b1,
        const float* __restrict__ sf_w2, const float* __restrict__ sf_b2)
{
    extern __shared__ float smem[];
    float* s_nt  = smem;            // 32*128 = 4096 floats (neigh, then t)
    float* s_ft  = smem + 4096;     // 32*32 = 1024
    float* s_b1  = smem + 5120;     // 128
    float* s_b2  = smem + 5248;     // 128
    int*   s_pred = (int*)(smem + 5376);  // 256 ints
    // total 5632 floats = 22528 B

    const int tid  = threadIdx.x;
    const int row0 = blockIdx.x * 32;

    // ---- preload ft, pred, biases ----
    for (int i = tid; i < 256; i += 128) {
        int r = i >> 3, c4 = i & 7;
        ((float4*)(s_ft + r * 32))[c4] =
            *((const float4*)(feat + (long long)(lo + row0 + r) * 32) + c4);
    }
    for (int i = tid; i < 256; i += 128)
        s_pred[i] = pred[(long long)row0 * KK + i];
    if (tid < 128) {
        s_b1[tid] = (tid < 64) ? ne_b1[tid] : sf_b1[tid - 64];
        s_b2[tid] = ne_b2[tid] + sf_b2[tid];
    }
    __syncthreads();

    // ---- gather mean of 8 predecessor rows (warp = one h row per task) ----
#pragma unroll
    for (int j = 0; j < 8; j++) {
        int task = tid + j * 128;
        int r = task >> 5, c4 = task & 31;
        const int* pr = s_pred + r * 8;
        float x = 0.f, y = 0.f, z = 0.f, ww = 0.f;
#pragma unroll
        for (int k = 0; k < 8; k++) {
            const float4 v = *((const float4*)(g_h + (long long)pr[k] * HH) + c4);
            x += v.x; y += v.y; z += v.z; ww += v.w;
        }
        *((float4*)(s_nt + r * 128) + c4) =
            make_float4(x * 0.125f, y * 0.125f, z * 0.125f, ww * 0.125f);
    }
    __syncthreads();   // ONLY block sync after preload: gather is cross-warp

    const int w = tid >> 5, l = tid & 31;     // 4 warps; warp owns 8 rows
    const int r0 = w * 8;
    // stage-1 mapping: half-warp = 4 rows, (l&15)*4 = 4 cols
    const int r1 = r0 + (l >> 4) * 4;
    const int cg = (l & 15) * 4;

    // ---- stage 1, ne path: k=128, weights streamed from global ----
    float accA[4][4];
#pragma unroll
    for (int i = 0; i < 4; i++)
#pragma unroll
        for (int c = 0; c < 4; c++) accA[i][c] = 0.f;

#pragma unroll 2
    for (int k = 0; k < 128; k += 4) {
        float4 wv0 = *(const float4*)(ne_w1 + (k + 0) * 64 + cg);
        float4 wv1 = *(const float4*)(ne_w1 + (k + 1) * 64 + cg);
        float4 wv2 = *(const float4*)(ne_w1 + (k + 2) * 64 + cg);
        float4 wv3 = *(const float4*)(ne_w1 + (k + 3) * 64 + cg);
#pragma unroll
        for (int i = 0; i < 4; i++) {
            float4 a = *(const float4*)(s_nt + (r1 + i) * 128 + k);
            accA[i][0] = fmaf(a.x, wv0.x, accA[i][0]); accA[i][0] = fmaf(a.y, wv1.x, accA[i][0]);
            accA[i][0] = fmaf(a.z, wv2.x, accA[i][0]); accA[i][0] = fmaf(a.w, wv3.x, accA[i][0]);
            accA[i][1] = fmaf(a.x, wv0.y, accA[i][1]); accA[i][1] = fmaf(a.y, wv1.y, accA[i][1]);
            accA[i][1] = fmaf(a.z, wv2.y, accA[i][1]); accA[i][1] = fmaf(a.w, wv3.y, accA[i][1]);
            accA[i][2] = fmaf(a.x, wv0.z, accA[i][2]); accA[i][2] = fmaf(a.y, wv1.z, accA[i][2]);
            accA[i][2] = fmaf(a.z, wv2.z, accA[i][2]); accA[i][2] = fmaf(a.w, wv3.z, accA[i][2]);
            accA[i][3] = fmaf(a.x, wv0.w, accA[i][3]); accA[i][3] = fmaf(a.y, wv1.w, accA[i][3]);
            accA[i][3] = fmaf(a.z, wv2.w, accA[i][3]); accA[i][3] = fmaf(a.w, wv3.w, accA[i][3]);
        }
    }
    __syncwarp();   // all lanes done reading neigh before t_ne overwrites

    // t_ne -> s_nt cols [cg, cg+4) of own 4 rows
#pragma unroll
    for (int i = 0; i < 4; i++) {
        float4 o;
        o.x = lrelu(accA[i][0] + s_b1[cg + 0]);
        o.y = lrelu(accA[i][1] + s_b1[cg + 1]);
        o.z = lrelu(accA[i][2] + s_b1[cg + 2]);
        o.w = lrelu(accA[i][3] + s_b1[cg + 3]);
        *(float4*)(s_nt + (r1 + i) * 128 + cg) = o;
    }

    // ---- stage 1, sf path: k=32 over s_ft (weights from global) ----
    float accB[4][4];
#pragma unroll
    for (int i = 0; i < 4; i++)
#pragma unroll
        for (int c = 0; c < 4; c++) accB[i][c] = 0.f;

#pragma unroll 2
    for (int k = 0; k < 32; k += 4) {
        float4 wv0 = *(const float4*)(sf_w1 + (k + 0) * 64 + cg);
        float4 wv1 = *(const float4*)(sf_w1 + (k + 1) * 64 + cg);
        float4 wv2 = *(const float4*)(sf_w1 + (k + 2) * 64 + cg);
        float4 wv3 = *(const float4*)(sf_w1 + (k + 3) * 64 + cg);
#pragma unroll
        for (int i = 0; i < 4; i++) {
            float4 a = *(const float4*)(s_ft + (r1 + i) * 32 + k);
            accB[i][0] = fmaf(a.x, wv0.x, accB[i][0]); accB[i][0] = fmaf(a.y, wv1.x, accB[i][0]);
            accB[i][0] = fmaf(a.z, wv2.x, accB[i][0]); accB[i][0] = fmaf(a.w, wv3.x, accB[i][0]);
            accB[i][1] = fmaf(a.x, wv0.y, accB[i][1]); accB[i][1] = fmaf(a.y, wv1.y, accB[i][1]);
            accB[i][1] = fmaf(a.z, wv2.y, accB[i][1]); accB[i][1] = fmaf(a.w, wv3.y, accB[i][1]);
            accB[i][2] = fmaf(a.x, wv0.z, accB[i][2]); accB[i][2] = fmaf(a.y, wv1.z, accB[i][2]);
            accB[i][2] = fmaf(a.z, wv2.z, accB[i][2]); accB[i][2] = fmaf(a.w, wv3.z, accB[i][2]);
            accB[i][3] = fmaf(a.x, wv0.w, accB[i][3]); accB[i][3] = fmaf(a.y, wv1.w, accB[i][3]);
            accB[i][3] = fmaf(a.z, wv2.w, accB[i][3]); accB[i][3] = fmaf(a.w, wv3.w, accB[i][3]);
        }
    }
    // t_sf -> s_nt cols [64+cg, 64+cg+4) (neigh cols 64.. already consumed; t_ne
    // write + this write ordered vs stage-2 reads by the syncwarp below)
#pragma unroll
    for (int i = 0; i < 4; i++) {
        float4 o;
        o.x = lrelu(accB[i][0] + s_b1[64 + cg + 0]);
        o.y = lrelu(accB[i][1] + s_b1[64 + cg + 1]);
        o.z = lrelu(accB[i][2] + s_b1[64 + cg + 2]);
        o.w = lrelu(accB[i][3] + s_b1[64 + cg + 3]);
        *(float4*)(s_nt + (r1 + i) * 128 + 64 + cg) = o;
    }
    __syncwarp();   // t complete for this warp's 8 rows (all warp-local)

    // ---- stage 2: k=128 (ne_w2 for t cols 0..63, sf_w2 for 64..127) ----
    const int c0 = l * 4;
    float acc[8][4];
#pragma unroll
    for (int r = 0; r < 8; r++) { acc[r][0] = acc[r][1] = acc[r][2] = acc[r][3] = 0.f; }

#pragma unroll 2
    for (int k = 0; k < 64; k += 4) {
        float4 wv0 = *(const float4*)(ne_w2 + (k + 0) * 128 + c0);
        float4 wv1 = *(const float4*)(ne_w2 + (k + 1) * 128 + c0);
        float4 wv2 = *(const float4*)(ne_w2 + (k + 2) * 128 + c0);
        float4 wv3 = *(const float4*)(ne_w2 + (k + 3) * 128 + c0);
#pragma unroll
        for (int r = 0; r < 8; r++) {
            float4 a = *(const float4*)(s_nt + (r0 + r) * 128 + k);
            acc[r][0] = fmaf(a.x, wv0.x, acc[r][0]); acc[r][0] = fmaf(a.y, wv1.x, acc[r][0]);
            acc[r][0] = fmaf(a.z, wv2.x, acc[r][0]); acc[r][0] = fmaf(a.w, wv3.x, acc[r][0]);
            acc[r][1] = fmaf(a.x, wv0.y, acc[r][1]); acc[r][1] = fmaf(a.y, wv1.y, acc[r][1]);
            acc[r][1] = fmaf(a.z, wv2.y, acc[r][1]); acc[r][1] = fmaf(a.w, wv3.y, acc[r][1]);
            acc[r][2] = fmaf(a.x, wv0.z, acc[r][2]); acc[r][2] = fmaf(a.y, wv1.z, acc[r][2]);
            acc[r][2] = fmaf(a.z, wv2.z, acc[r][2]); acc[r][2] = fmaf(a.w, wv3.z, acc[r][2]);
            acc[r][3] = fmaf(a.x, wv0.w, acc[r][3]); acc[r][3] = fmaf(a.y, wv1.w, acc[r][3]);
            acc[r][3] = fmaf(a.z, wv2.w, acc[r][3]); acc[r][3] = fmaf(a.w, wv3.w, acc[r][3]);
        }
    }
#pragma unroll 2
    for (int k = 0; k < 64; k += 4) {
        float4 wv0 = *(const float4*)(sf_w2 + (k + 0) * 128 + c0);
        float4 wv1 = *(const float4*)(sf_w2 + (k + 1) * 128 + c0);
        float4 wv2 = *(const float4*)(sf_w2 + (k + 2) * 128 + c0);
        float4 wv3 = *(const float4*)(sf_w2 + (k + 3) * 128 + c0);
#pragma unroll
        for (int r = 0; r < 8; r++) {
            float4 a = *(const float4*)(s_nt + (r0 + r) * 128 + 64 + k);
            acc[r][0] = fmaf(a.x, wv0.x, acc[r][0]); acc[r][0] = fmaf(a.y, wv1.x, acc[r][0]);
            acc[r][0] = fmaf(a.z, wv2.x, acc[r][0]); acc[r][0] = fmaf(a.w, wv3.x, acc[r][0]);
            acc[r][1] = fmaf(a.x, wv0.y, acc[r][1]); acc[r][1] = fmaf(a.y, wv1.y, acc[r][1]);
            acc[r][1] = fmaf(a.z, wv2.y, acc[r][1]); acc[r][1] = fmaf(a.w, wv3.y, acc[r][1]);
            acc[r][2] = fmaf(a.x, wv0.z, acc[r][2]); acc[r][2] = fmaf(a.y, wv1.z, acc[r][2]);
            acc[r][2] = fmaf(a.z, wv2.z, acc[r][2]); acc[r][2] = fmaf(a.w, wv3.z, acc[r][2]);
            acc[r][3] = fmaf(a.x, wv0.w, acc[r][3]); acc[r][3] = fmaf(a.y, wv1.w, acc[r][3]);
            acc[r][3] = fmaf(a.z, wv2.w, acc[r][3]); acc[r][3] = fmaf(a.w, wv3.w, acc[r][3]);
        }
    }

    // ---- epilogue ----
#pragma unroll
    for (int r = 0; r < 8; r++) {
        float4 o;
        o.x = acc[r][0] + s_b2[c0 + 0];
        o.y = acc[r][1] + s_b2[c0 + 1];
        o.z = acc[r][2] + s_b2[c0 + 2];
        o.w = acc[r][3] + s_b2[c0 + 3];
        if (DO_RELU) { o.x = relu_(o.x); o.y = relu_(o.y); o.z = relu_(o.z); o.w = relu_(o.w); }
        *(float4*)(g_h + (long long)(lo + row0 + r0 + r) * HH + c0) = o;
    }
}

// ---------------------------------------------------------------------------
// Final head (unchanged)
// ---------------------------------------------------------------------------
__global__ void __launch_bounds__(256, 1)
k_final(const float* __restrict__ PO,
        const float* __restrict__ gl_w1, const float* __restrict__ gl_b1,
        const float* __restrict__ gl_w2, const float* __restrict__ gl_b2,
        const float* __restrict__ out_w1, const float* __restrict__ out_b1,
        const float* __restrict__ out_w2, const float* __restrict__ out_b2,
        float* __restrict__ out)
{
    extern __shared__ float smem[];
    float* s_x   = smem;             // 64*256
    float* s_w   = s_x + 16384;      // 64*128
    float* s_t   = s_w + 8192;       // 64*132
    float* s_g1  = s_t + 8448;       // 64*64
    float* s_gb2 = s_g1 + 4096;      // 128
    float* s_ob1 = s_gb2 + 128;      // 128
    float* s_ow2 = s_ob1 + 128;      // 128

    const int tid  = threadIdx.x;
    const int row0 = blockIdx.x * 64;
    const long long gnn0 = (long long)(LL - 1) * PP * HH;

    for (int i = tid; i < 2048; i += 256)
        ((float4*)s_w)[i] = ((const float4*)gl_w2)[i];
    for (int i = tid; i < 128; i += 256) {
        s_gb2[i] = gl_b2[i];
        s_ob1[i] = out_b1[i];
        s_ow2[i] = out_w2[i];
    }
    for (int i = tid; i < 64 * 64; i += 256) {
        int r = i >> 6, c = i & 63;
        s_g1[i] = lrelu(PO[row0 + r] * gl_w1[c] + gl_b1[c]);
    }
    for (int i = tid; i < 2048; i += 256) {
        int r = i >> 5, c4 = i & 31;
        float4 v = *((const float4*)(g_h + gnn0 + (long long)(row0 + r) * HH) + c4);
        *((float4*)(s_x + r * 256) + c4) = v;
    }
    __syncthreads();

    const int w = tid >> 5, l = tid & 31;
    const int r0 = w * 8, c0 = l * 4;

    {
        float acc[8][4];
#pragma unroll
        for (int r = 0; r < 8; r++) { acc[r][0] = acc[r][1] = acc[r][2] = acc[r][3] = 0.f; }
#pragma unroll 4
        for (int k = 0; k < 64; k += 2) {
            float4 w0  = *(const float4*)(s_w + k * 128 + c0);
            float4 w1v = *(const float4*)(s_w + (k + 1) * 128 + c0);
#pragma unroll
            for (int r = 0; r < 8; r++) {
                float2 a = *(const float2*)(s_g1 + (r0 + r) * 64 + k);
                acc[r][0] = fmaf(a.x, w0.x, acc[r][0]); acc[r][0] = fmaf(a.y, w1v.x, acc[r][0]);
                acc[r][1] = fmaf(a.x, w0.y, acc[r][1]); acc[r][1] = fmaf(a.y, w1v.y, acc[r][1]);
                acc[r][2] = fmaf(a.x, w0.z, acc[r][2]); acc[r][2] = fmaf(a.y, w1v.z, acc[r][2]);
                acc[r][3] = fmaf(a.x, w0.w, acc[r][3]); acc[r][3] = fmaf(a.y, w1v.w, acc[r][3]);
            }
        }
#pragma unroll
        for (int r = 0; r < 8; r++) {
            float4 o;
            o.x = acc[r][0] + s_gb2[c0 + 0];
            o.y = acc[r][1] + s_gb2[c0 + 1];
            o.z = acc[r][2] + s_gb2[c0 + 2];
            o.w = acc[r][3] + s_gb2[c0 + 3];
            *(float4*)(s_x + (r0 + r) * 256 + 128 + c0) = o;
        }
    }

    float acc[8][4];
#pragma unroll
    for (int r = 0; r < 8; r++) { acc[r][0] = acc[r][1] = acc[r][2] = acc[r][3] = 0.f; }
    for (int kt = 0; kt < 4; kt++) {
        __syncthreads();
        const float4* src = (const float4*)(out_w1 + kt * 64 * 128);
        for (int i = tid; i < 2048; i += 256) ((float4*)s_w)[i] = src[i];
        __syncthreads();
#pragma unroll 4
        for (int k = 0; k < 64; k += 2) {
            float4 w0  = *(const float4*)(s_w + k * 128 + c0);
            float4 w1v = *(const float4*)(s_w + (k + 1) * 128 + c0);
#pragma unroll
            for (int r = 0; r < 8; r++) {
                float2 a = *(const float2*)(s_x + (r0 + r) * 256 + kt * 64 + k);
                acc[r][0] = fmaf(a.x, w0.x, acc[r][0]); acc[r][0] = fmaf(a.y, w1v.x, acc[r][0]);
                acc[r][1] = fmaf(a.x, w0.y, acc[r][1]); acc[r][1] = fmaf(a.y, w1v.y, acc[r][1]);
                acc[r][2] = fmaf(a.x, w0.z, acc[r][2]); acc[r][2] = fmaf(a.y, w1v.z, acc[r][2]);
                acc[r][3] = fmaf(a.x, w0.w, acc[r][3]); acc[r][3] = fmaf(a.y, w1v.w, acc[r][3]);
            }
        }
    }
#pragma unroll
    for (int r = 0; r < 8; r++) {
        float* t = s_t + (r0 + r) * 132;
        t[c0 + 0] = lrelu(acc[r][0] + s_ob1[c0 + 0]);
        t[c0 + 1] = lrelu(acc[r][1] + s_ob1[c0 + 1]);
        t[c0 + 2] = lrelu(acc[r][2] + s_ob1[c0 + 2]);
        t[c0 + 3] = lrelu(acc[r][3] + s_ob1[c0 + 3]);
    }
    __syncthreads();

    if (tid < 64) {
        float s = out_b2[0];
        const float* t = s_t + tid * 132;
#pragma unroll 8
        for (int k = 0; k < 128; k++) s = fmaf(t[k], s_ow2[k], s);
        out[row0 + tid] = s;
    }
}

// ---------------------------------------------------------------------------
extern "C" void kernel_launch(void* const* d_in, const int* in_sizes, int n_in,
                              void* d_out, int out_size)
{
    // Disambiguate input ordering via in_sizes[3] (pred=3932160 vs pi_w1=64).
    int idx_pred, idx_ispo, wbase;
    if (in_sizes[3] == (LL - 1) * PP * KK) { idx_pred = 3; idx_ispo = 4; wbase = 5; }
    else                                   { idx_pred = 23; idx_ispo = 24; wbase = 3; }
    (void)idx_ispo;

    const float* delay  = (const float*)d_in[0];
    const float* feat   = (const float*)d_in[1];
    const float* PO     = (const float*)d_in[2];
    const int*   pred   = (const int*)d_in[idx_pred];
    const float* pi_w1  = (const float*)d_in[wbase + 0];
    const float* pi_b1  = (const float*)d_in[wbase + 1];
    const float* pi_w2  = (const float*)d_in[wbase + 2];
    const float* pi_b2  = (const float*)d_in[wbase + 3];
    const float* ne_w1  = (const float*)d_in[wbase + 4];
    const float* ne_b1  = (const float*)d_in[wbase + 5];
    const float* ne_w2  = (const float*)d_in[wbase + 6];
    const float* ne_b2  = (const float*)d_in[wbase + 7];
    const float* sf_w1  = (const float*)d_in[wbase + 8];
    const float* sf_b1  = (const float*)d_in[wbase + 9];
    const float* sf_w2  = (const float*)d_in[wbase + 10];
    const float* sf_b2  = (const float*)d_in[wbase + 11];
    const float* gl_w1  = (const float*)d_in[wbase + 12];
    const float* gl_b1  = (const float*)d_in[wbase + 13];
    const float* gl_w2  = (const float*)d_in[wbase + 14];
    const float* gl_b2  = (const float*)d_in[wbase + 15];
    const float* out_w1 = (const float*)d_in[wbase + 16];
    const float* out_b1 = (const float*)d_in[wbase + 17];
    const float* out_w2 = (const float*)d_in[wbase + 18];
    const float* out_b2 = (const float*)d_in[wbase + 19];
    float* out = (float*)d_out;

    const size_t sh_init  = (size_t)(64 * 64 + 64 * 128 + 128) * 4;
    // layer: nt 4096 + ft 1024 + b1 128 + b2 128 + pred 256 = 5632 floats = 22528B
    const size_t sh_layer = (size_t)5632 * 4;
    const size_t sh_final = (size_t)(16384 + 8192 + 8448 + 4096 + 128 + 128 + 128) * 4;

    cudaFuncSetAttribute(k_init,  cudaFuncAttributeMaxDynamicSharedMemorySize, (int)sh_init);
    cudaFuncSetAttribute(k_layer<true>,  cudaFuncAttributeMaxDynamicSharedMemorySize, (int)sh_layer);
    cudaFuncSetAttribute(k_layer<false>, cudaFuncAttributeMaxDynamicSharedMemorySize, (int)sh_layer);
    cudaFuncSetAttribute(k_final, cudaFuncAttributeMaxDynamicSharedMemorySize, (int)sh_final);

    k_init<<<PP / 64, 256, sh_init>>>(delay, pi_w1, pi_b1, pi_w2, pi_b2);
    for (int i = 1; i < LL; i++) {
        const int* pl = pred + (long long)(i - 1) * PP * KK;
        if (i < LL - 1)
            k_layer<true><<<PP / 32, 128, sh_layer>>>(i * PP, pl, feat,
                ne_w1, ne_b1, ne_w2, ne_b2, sf_w1, sf_b1, sf_w2, sf_b2);
        else
            k_layer<false><<<PP / 32, 128, sh_layer>>>(i * PP, pl, feat,
                ne_w1, ne_b1, ne_w2, ne_b2, sf_w1, sf_b1, sf_w2, sf_b2);
    }
    k_final<<<PP / 64, 256, sh_final>>>(PO, gl_w1, gl_b1, gl_w2, gl_b2,
                                        out_w1, out_b1, out_w2, out_b2, out);
}